// round 4
// baseline (speedup 1.0000x reference)
#include <cuda_runtime.h>
#include <cuda_bf16.h>
#include <math.h>

// ---------------- problem constants ----------------
#define D_MODEL 512
#define HEADS   8
#define DK      64
#define N_LAYERS 4
#define BS      16
#define SEQ     4096
#define EPS     1e-6f
#define ROWS    (BS * SEQ)              // 65536
#define INV_SQRT_DK 0.125f              // 1/sqrt(64)
#define SCHUNKS 32                      // seq chunks for column-sum stage 1

typedef unsigned long long ull;

// ---------------- scratch (device globals; no allocation allowed) ----------
__device__ float g_x[(size_t)ROWS * D_MODEL];   // layer input / z buffer
__device__ float g_y[(size_t)ROWS * D_MODEL];   // norm1 output
__device__ float g_v[(size_t)ROWS * D_MODEL];   // v projection
__device__ float g_c[(size_t)ROWS * D_MODEL];   // concat (out of per-head matmul)
__device__ float g_part[(size_t)BS * SCHUNKS * D_MODEL]; // colsum partials
__device__ float g_ksum[BS * D_MODEL];
__device__ float g_M[(size_t)BS * HEADS * DK * DK];      // scores + I

__device__ __forceinline__ float2 u2f2(ull u) {
    float2 f;
    f.x = __uint_as_float((unsigned)u);
    f.y = __uint_as_float((unsigned)(u >> 32));
    return f;
}

// ---------------- layernorm (unbiased std, eps added to std) ---------------
// one block per row, 128 threads * float4
// in_sel: 0 -> ext_in, 1 -> g_x ; out_sel: 0 -> ext_out, 1 -> g_y, 2 -> g_x
__global__ void norm_kernel(const float* __restrict__ ext_in,
                            const float* __restrict__ alpha,
                            const float* __restrict__ beta,
                            float* __restrict__ ext_out,
                            int in_sel, int out_sel)
{
    const float* in = in_sel ? g_x : ext_in;
    float* out = (out_sel == 0) ? ext_out : (out_sel == 1 ? g_y : g_x);

    size_t row = blockIdx.x;
    int tid = threadIdx.x;          // 0..127
    const float4 v = ((const float4*)(in + row * D_MODEL))[tid];

    float s  = v.x + v.y + v.z + v.w;
    float ss = v.x * v.x + v.y * v.y + v.z * v.z + v.w * v.w;

    #pragma unroll
    for (int o = 16; o > 0; o >>= 1) {
        s  += __shfl_xor_sync(0xffffffffu, s,  o);
        ss += __shfl_xor_sync(0xffffffffu, ss, o);
    }
    __shared__ float sh[8];
    int wid = tid >> 5, lane = tid & 31;
    if (lane == 0) { sh[wid] = s; sh[4 + wid] = ss; }
    __syncthreads();
    s  = sh[0] + sh[1] + sh[2] + sh[3];
    ss = sh[4] + sh[5] + sh[6] + sh[7];

    float mean = s * (1.0f / D_MODEL);
    float var  = (ss - (float)D_MODEL * mean * mean) * (1.0f / (D_MODEL - 1));
    var = fmaxf(var, 0.0f);
    float r = 1.0f / (sqrtf(var) + EPS);

    float4 a4 = ((const float4*)alpha)[tid];
    float4 b4 = ((const float4*)beta)[tid];
    float4 o4;
    o4.x = a4.x * (v.x - mean) * r + b4.x;
    o4.y = a4.y * (v.y - mean) * r + b4.y;
    o4.z = a4.z * (v.z - mean) * r + b4.z;
    o4.w = a4.w * (v.w - mean) * r + b4.w;
    ((float4*)(out + row * D_MODEL))[tid] = o4;
}

// ---------------- column sum of y over seq, deterministic two-stage --------
// stage 1: grid = BS * (D/256) * SCHUNKS blocks, 256 threads
__global__ void colsum_kernel()
{
    int bx = blockIdx.x;                        // 0..1023
    int b  = bx >> 6;
    int rem = bx & 63;
    int cb = rem >> 5;                          // 0..1 (channel halves)
    int sc = rem & 31;                          // seq chunk
    int c  = cb * 256 + threadIdx.x;

    const float* p = g_y + ((size_t)b * SEQ + (size_t)sc * 128) * D_MODEL + c;
    float a0 = 0.f, a1 = 0.f, a2 = 0.f, a3 = 0.f;
    #pragma unroll 8
    for (int s = 0; s < 128; s += 4) {
        a0 += p[(size_t)(s + 0) * D_MODEL];
        a1 += p[(size_t)(s + 1) * D_MODEL];
        a2 += p[(size_t)(s + 2) * D_MODEL];
        a3 += p[(size_t)(s + 3) * D_MODEL];
    }
    g_part[((size_t)b * SCHUNKS + sc) * D_MODEL + c] = (a0 + a1) + (a2 + a3);
}

// stage 2: 8192 threads
__global__ void ksum_reduce_kernel()
{
    int idx = blockIdx.x * 256 + threadIdx.x;   // 0..8191
    int b = idx >> 9;
    int c = idx & (D_MODEL - 1);
    float s = 0.f;
    #pragma unroll
    for (int k = 0; k < SCHUNKS; k++)
        s += g_part[((size_t)b * SCHUNKS + k) * D_MODEL + c];
    g_ksum[idx] = s;
}

// ---------------- scores: M = softmax_j(convw[c]*ks[j]/sqrt(dk)+...) + I ---
// grid = BS*HEADS blocks, 64 threads (thread = column c)
__global__ void scores_kernel(const float* __restrict__ convw,
                              const float* __restrict__ convb)
{
    __shared__ float ks[DK];
    int bh = blockIdx.x;
    int b = bh / HEADS, h = bh % HEADS;
    int c = threadIdx.x;
    ks[c] = g_ksum[b * D_MODEL + h * DK + c];
    __syncthreads();

    float w  = convw[c] * INV_SQRT_DK;
    float bb = (float)SEQ * convb[c] * INV_SQRT_DK;   // constant in j (cancels)

    float logit[DK];
    float mx = -1e30f;
    #pragma unroll
    for (int j = 0; j < DK; j++) {
        logit[j] = fmaf(w, ks[j], bb);
        mx = fmaxf(mx, logit[j]);
    }
    float sum = 0.f;
    #pragma unroll
    for (int j = 0; j < DK; j++) {
        logit[j] = expf(logit[j] - mx);
        sum += logit[j];
    }
    float inv = 1.0f / sum;
    float* Mp = g_M + (size_t)bh * DK * DK;
    #pragma unroll
    for (int j = 0; j < DK; j++)
        Mp[j * DK + c] = logit[j] * inv + (j == c ? 1.0f : 0.0f);
}

// ---------------- big SGEMM: C = A @ W^T + bias (opt relu + residual) ------
// A: [ROWS, 512] row-major; W: [512,512] row-major (we need W^T)
// MODE 0: A=g_y -> C=g_v (bias only)
// MODE 1: A=g_c -> C=g_x, C = g_y + relu(acc + bias)
// 128x128x16 tiles, 256 threads, 8x8 per thread using packed fma.rn.f32x2
template <int MODE>
__global__ __launch_bounds__(256, 2)
void sgemm_kernel(const float* __restrict__ W, const float* __restrict__ bias)
{
    const float* A = (MODE == 0) ? g_y : g_c;
    float*       C = (MODE == 0) ? g_v : g_x;

    const int BK = 16;
    __shared__ __align__(16) float As[BK][128];
    __shared__ __align__(16) float Bs[BK][128];

    int bn = blockIdx.x;            // 0..3
    int bm = blockIdx.y;            // 0..511
    int tid = threadIdx.x;
    int tm = (tid >> 4) * 8;        // 0..120
    int tn = (tid & 15) * 8;        // 0..120

    int lr  = tid >> 2;             // 0..63
    int lk4 = (tid & 3) * 4;        // 0,4,8,12

    const float* Ag = A + (size_t)bm * 128 * D_MODEL;
    const float* Wg = W + (size_t)bn * 128 * D_MODEL;

    ull acc[8][4];
    #pragma unroll
    for (int i = 0; i < 8; i++)
        #pragma unroll
        for (int j = 0; j < 4; j++) acc[i][j] = 0ull;

    for (int k0 = 0; k0 < D_MODEL; k0 += BK) {
        #pragma unroll
        for (int i = 0; i < 2; i++) {
            int m = lr + i * 64;
            float4 a = *(const float4*)(Ag + (size_t)m * D_MODEL + k0 + lk4);
            As[lk4 + 0][m] = a.x; As[lk4 + 1][m] = a.y;
            As[lk4 + 2][m] = a.z; As[lk4 + 3][m] = a.w;
        }
        #pragma unroll
        for (int i = 0; i < 2; i++) {
            int n = lr + i * 64;
            float4 b = *(const float4*)(Wg + (size_t)n * D_MODEL + k0 + lk4);
            Bs[lk4 + 0][n] = b.x; Bs[lk4 + 1][n] = b.y;
            Bs[lk4 + 2][n] = b.z; Bs[lk4 + 3][n] = b.w;
        }
        __syncthreads();

        #pragma unroll
        for (int k = 0; k < BK; k++) {
            float4 a0 = *(const float4*)&As[k][tm];
            float4 a1 = *(const float4*)&As[k][tm + 4];
            ull b0 = *(const ull*)&Bs[k][tn];
            ull b1 = *(const ull*)&Bs[k][tn + 2];
            ull b2 = *(const ull*)&Bs[k][tn + 4];
            ull b3 = *(const ull*)&Bs[k][tn + 6];
            float av[8] = {a0.x, a0.y, a0.z, a0.w, a1.x, a1.y, a1.z, a1.w};
            #pragma unroll
            for (int i = 0; i < 8; i++) {
                unsigned au = __float_as_uint(av[i]);
                ull a2;
                asm("mov.b64 %0, {%1, %1};" : "=l"(a2) : "r"(au));
                asm("fma.rn.f32x2 %0, %1, %2, %0;" : "+l"(acc[i][0]) : "l"(a2), "l"(b0));
                asm("fma.rn.f32x2 %0, %1, %2, %0;" : "+l"(acc[i][1]) : "l"(a2), "l"(b1));
                asm("fma.rn.f32x2 %0, %1, %2, %0;" : "+l"(acc[i][2]) : "l"(a2), "l"(b2));
                asm("fma.rn.f32x2 %0, %1, %2, %0;" : "+l"(acc[i][3]) : "l"(a2), "l"(b3));
            }
        }
        __syncthreads();
    }

    int col0 = bn * 128 + tn;
    float bvv[8];
    {
        float4 bA = *(const float4*)(bias + col0);
        float4 bB = *(const float4*)(bias + col0 + 4);
        bvv[0] = bA.x; bvv[1] = bA.y; bvv[2] = bA.z; bvv[3] = bA.w;
        bvv[4] = bB.x; bvv[5] = bB.y; bvv[6] = bB.z; bvv[7] = bB.w;
    }

    #pragma unroll
    for (int i = 0; i < 8; i++) {
        size_t row = (size_t)bm * 128 + tm + i;
        float o[8];
        #pragma unroll
        for (int jj = 0; jj < 4; jj++) {
            float2 f = u2f2(acc[i][jj]);
            o[2 * jj + 0] = f.x + bvv[2 * jj + 0];
            o[2 * jj + 1] = f.y + bvv[2 * jj + 1];
        }
        if (MODE == 1) {
            const float* rr = g_y + row * D_MODEL + col0;
            float4 r0 = *(const float4*)rr;
            float4 r1 = *(const float4*)(rr + 4);
            float rv[8] = {r0.x, r0.y, r0.z, r0.w, r1.x, r1.y, r1.z, r1.w};
            #pragma unroll
            for (int j = 0; j < 8; j++) o[j] = rv[j] + fmaxf(o[j], 0.0f);
        }
        float* crow = C + row * D_MODEL + col0;
        float4 s0 = make_float4(o[0], o[1], o[2], o[3]);
        float4 s1 = make_float4(o[4], o[5], o[6], o[7]);
        *(float4*)crow = s0;
        *(float4*)(crow + 4) = s1;
    }
}

// ---------------- per-head out = v_head @ M (M = scores + I) ---------------
// grid = (SEQ/64, BS*HEADS), 256 threads; 64 rows x 64 cols per block
__global__ __launch_bounds__(256)
void outmm_kernel()
{
    __shared__ __align__(16) float Vs[DK][68];  // [j][m] transposed
    __shared__ __align__(16) float Ms[DK][68];  // [j][c]

    int bh = blockIdx.y;
    int b = bh / HEADS, h = bh % HEADS;
    int s0 = blockIdx.x * 64;
    int tid = threadIdx.x;

    // load M tile
    #pragma unroll
    for (int t = 0; t < 16; t++) {
        int lin = tid + 256 * t;                 // 0..4095
        int j = lin >> 6, c = lin & 63;
        Ms[j][c] = g_M[((size_t)bh * DK + j) * DK + c];
    }
    // load V tile transposed
    #pragma unroll
    for (int t = 0; t < 4; t++) {
        int lin = tid + 256 * t;                 // 0..1023
        int m = lin >> 4, q = lin & 15;
        float4 f = *(const float4*)(g_v + ((size_t)b * SEQ + s0 + m) * D_MODEL
                                        + h * DK + q * 4);
        Vs[q * 4 + 0][m] = f.x;
        Vs[q * 4 + 1][m] = f.y;
        Vs[q * 4 + 2][m] = f.z;
        Vs[q * 4 + 3][m] = f.w;
    }
    __syncthreads();

    int tm = (tid >> 4) * 4;     // 0..60
    int tc = (tid & 15) * 4;     // 0..60

    ull acc[4][2];
    #pragma unroll
    for (int i = 0; i < 4; i++) { acc[i][0] = 0ull; acc[i][1] = 0ull; }

    #pragma unroll
    for (int j = 0; j < DK; j++) {
        float4 a = *(const float4*)&Vs[j][tm];
        ull b0 = *(const ull*)&Ms[j][tc];
        ull b1 = *(const ull*)&Ms[j][tc + 2];
        float av[4] = {a.x, a.y, a.z, a.w};
        #pragma unroll
        for (int i = 0; i < 4; i++) {
            unsigned au = __float_as_uint(av[i]);
            ull a2;
            asm("mov.b64 %0, {%1, %1};" : "=l"(a2) : "r"(au));
            asm("fma.rn.f32x2 %0, %1, %2, %0;" : "+l"(acc[i][0]) : "l"(a2), "l"(b0));
            asm("fma.rn.f32x2 %0, %1, %2, %0;" : "+l"(acc[i][1]) : "l"(a2), "l"(b1));
        }
    }

    #pragma unroll
    for (int i = 0; i < 4; i++) {
        size_t base = ((size_t)b * SEQ + s0 + tm + i) * D_MODEL + h * DK + tc;
        float2 f0 = u2f2(acc[i][0]);
        float2 f1 = u2f2(acc[i][1]);
        *(float2*)(g_c + base)     = f0;
        *(float2*)(g_c + base + 2) = f1;
    }
}

// ---------------- driver ----------------------------------------------------
extern "C" void kernel_launch(void* const* d_in, const int* in_sizes, int n_in,
                              void* d_out, int out_size)
{
    const float* x    = (const float*)d_in[0];
    const float* Wv   = (const float*)d_in[1];
    const float* bv   = (const float*)d_in[2];
    const float* cw   = (const float*)d_in[3];
    const float* cb   = (const float*)d_in[4];
    const float* Wo   = (const float*)d_in[5];
    const float* bo   = (const float*)d_in[6];
    const float* a1   = (const float*)d_in[7];
    const float* b1   = (const float*)d_in[8];
    const float* a2   = (const float*)d_in[9];
    const float* b2   = (const float*)d_in[10];
    float* out = (float*)d_out;

    for (int L = 0; L < N_LAYERS; L++) {
        // y = norm1(x)
        norm_kernel<<<ROWS, 128>>>(x, a1 + L * D_MODEL, b1 + L * D_MODEL,
                                   nullptr, (L == 0) ? 0 : 1, 1);
        // ksum = sum_s y
        colsum_kernel<<<BS * 2 * SCHUNKS, 256>>>();
        ksum_reduce_kernel<<<32, 256>>>();
        // M = softmax + I
        scores_kernel<<<BS * HEADS, 64>>>(cw + L * DK, cb + L * DK);
        // v = y @ Wv^T + bv
        sgemm_kernel<0><<<dim3(4, 512), 256>>>(Wv + (size_t)L * D_MODEL * D_MODEL,
                                               bv + L * D_MODEL);
        // concat = per-head v @ M
        outmm_kernel<<<dim3(SEQ / 64, BS * HEADS), 256>>>();
        // z = y + relu(concat @ Wo^T + bo)
        sgemm_kernel<1><<<dim3(4, 512), 256>>>(Wo + (size_t)L * D_MODEL * D_MODEL,
                                               bo + L * D_MODEL);
        // x = norm2(z)  (last layer -> d_out)
        norm_kernel<<<ROWS, 128>>>(nullptr, a2 + L * D_MODEL, b2 + L * D_MODEL,
                                   out, 1, (L == N_LAYERS - 1) ? 0 : 2);
    }
}

// round 11
// speedup vs baseline: 1.8281x; 1.8281x over previous
#include <cuda_runtime.h>
#include <cuda_bf16.h>
#include <math.h>

// ---------------- problem constants ----------------
#define D_MODEL 512
#define HEADS   8
#define DK      64
#define N_LAYERS 4
#define BS      16
#define SEQ     4096
#define EPS     1e-6f
#define ROWS    (BS * SEQ)              // 65536
#define INV_SQRT_DK 0.125f
#define SCHUNKS 32

typedef unsigned long long ull;

// ---------------- scratch (device globals) ----------------------------------
__device__ float g_x[(size_t)ROWS * D_MODEL];   // layer input / z buffer
__device__ float g_y[(size_t)ROWS * D_MODEL];   // norm1 output (fp32)
__device__ float g_v[(size_t)ROWS * D_MODEL];   // v projection (fp32)
__device__ float g_c[(size_t)ROWS * D_MODEL];   // concat (fp32)
__device__ float g_part[(size_t)BS * SCHUNKS * D_MODEL];
__device__ float g_ksum[BS * D_MODEL];
__device__ float g_M[(size_t)BS * HEADS * DK * DK];
// pre-split bf16 weights (hi/lo), all layers  (accessed ONLY from device code)
__device__ __nv_bfloat16 g_Wvh[(size_t)N_LAYERS * D_MODEL * D_MODEL];
__device__ __nv_bfloat16 g_Wvl[(size_t)N_LAYERS * D_MODEL * D_MODEL];
__device__ __nv_bfloat16 g_Woh[(size_t)N_LAYERS * D_MODEL * D_MODEL];
__device__ __nv_bfloat16 g_Wol[(size_t)N_LAYERS * D_MODEL * D_MODEL];

// ---------------- helpers -----------------------------------------------------
__device__ __forceinline__ float2 u2f2(ull u) {
    float2 f;
    f.x = __uint_as_float((unsigned)u);
    f.y = __uint_as_float((unsigned)(u >> 32));
    return f;
}
__device__ __forceinline__ void bsplit(float v, __nv_bfloat16& h, __nv_bfloat16& l) {
    h = __float2bfloat16(v);
    l = __float2bfloat16(v - __bfloat162float(h));
}
__device__ __forceinline__ unsigned pack2(__nv_bfloat16 a, __nv_bfloat16 b) {
    __nv_bfloat162 p = __halves2bfloat162(a, b);
    return *reinterpret_cast<unsigned*>(&p);
}
__device__ __forceinline__ unsigned smem_u32(const void* p) {
    unsigned a;
    asm("{ .reg .u64 t; cvta.to.shared.u64 t, %1; cvt.u32.u64 %0, t; }"
        : "=r"(a) : "l"(p));
    return a;
}
__device__ __forceinline__ void mma16816(float* c, const unsigned* a, const unsigned* b) {
    asm volatile(
        "mma.sync.aligned.m16n8k16.row.col.f32.bf16.bf16.f32 "
        "{%0,%1,%2,%3}, {%4,%5,%6,%7}, {%8,%9}, {%0,%1,%2,%3};"
        : "+f"(c[0]), "+f"(c[1]), "+f"(c[2]), "+f"(c[3])
        : "r"(a[0]), "r"(a[1]), "r"(a[2]), "r"(a[3]), "r"(b[0]), "r"(b[1]));
}
__device__ __forceinline__ void ldsm4(unsigned* r, unsigned addr) {
    asm volatile("ldmatrix.sync.aligned.m8n8.x4.shared.b16 {%0,%1,%2,%3}, [%4];"
                 : "=r"(r[0]), "=r"(r[1]), "=r"(r[2]), "=r"(r[3]) : "r"(addr));
}

// ---------------- layernorm (R4-proven) ---------------------------------------
// in_sel: 0 -> ext_in, 1 -> g_x ; out_sel: 0 -> ext_out, 1 -> g_y, 2 -> g_x
__global__ void norm_kernel(const float* __restrict__ ext_in,
                            const float* __restrict__ alpha,
                            const float* __restrict__ beta,
                            float* __restrict__ ext_out,
                            int in_sel, int out_sel)
{
    const float* in = in_sel ? g_x : ext_in;
    float* out = (out_sel == 0) ? ext_out : (out_sel == 1 ? g_y : g_x);

    size_t row = blockIdx.x;
    int tid = threadIdx.x;
    const float4 v = ((const float4*)(in + row * D_MODEL))[tid];

    float s  = v.x + v.y + v.z + v.w;
    float ss = v.x * v.x + v.y * v.y + v.z * v.z + v.w * v.w;
    #pragma unroll
    for (int o = 16; o > 0; o >>= 1) {
        s  += __shfl_xor_sync(0xffffffffu, s,  o);
        ss += __shfl_xor_sync(0xffffffffu, ss, o);
    }
    __shared__ float sh[8];
    int wid = tid >> 5, lane = tid & 31;
    if (lane == 0) { sh[wid] = s; sh[4 + wid] = ss; }
    __syncthreads();
    s  = sh[0] + sh[1] + sh[2] + sh[3];
    ss = sh[4] + sh[5] + sh[6] + sh[7];

    float mean = s * (1.0f / D_MODEL);
    float var  = (ss - (float)D_MODEL * mean * mean) * (1.0f / (D_MODEL - 1));
    var = fmaxf(var, 0.0f);
    float r = 1.0f / (sqrtf(var) + EPS);

    float4 a4 = ((const float4*)alpha)[tid];
    float4 b4 = ((const float4*)beta)[tid];
    float4 o4;
    o4.x = a4.x * (v.x - mean) * r + b4.x;
    o4.y = a4.y * (v.y - mean) * r + b4.y;
    o4.z = a4.z * (v.z - mean) * r + b4.z;
    o4.w = a4.w * (v.w - mean) * r + b4.w;
    ((float4*)(out + row * D_MODEL))[tid] = o4;
}

// ---------------- column sum of y over seq (R4-proven) -------------------------
__global__ void colsum_kernel()
{
    int bx = blockIdx.x;
    int b  = bx >> 6;
    int rem = bx & 63;
    int cb = rem >> 5;
    int sc = rem & 31;
    int c  = cb * 256 + threadIdx.x;

    const float* p = g_y + ((size_t)b * SEQ + (size_t)sc * 128) * D_MODEL + c;
    float a0 = 0.f, a1 = 0.f, a2 = 0.f, a3 = 0.f;
    #pragma unroll 8
    for (int s = 0; s < 128; s += 4) {
        a0 += p[(size_t)(s + 0) * D_MODEL];
        a1 += p[(size_t)(s + 1) * D_MODEL];
        a2 += p[(size_t)(s + 2) * D_MODEL];
        a3 += p[(size_t)(s + 3) * D_MODEL];
    }
    g_part[((size_t)b * SCHUNKS + sc) * D_MODEL + c] = (a0 + a1) + (a2 + a3);
}

__global__ void ksum_reduce_kernel()
{
    int idx = blockIdx.x * 256 + threadIdx.x;
    int b = idx >> 9;
    int c = idx & (D_MODEL - 1);
    float s = 0.f;
    #pragma unroll
    for (int k = 0; k < SCHUNKS; k++)
        s += g_part[((size_t)b * SCHUNKS + k) * D_MODEL + c];
    g_ksum[idx] = s;
}

// ---------------- scores: M = softmax + I (R4-proven) --------------------------
__global__ void scores_kernel(const float* __restrict__ convw,
                              const float* __restrict__ convb)
{
    __shared__ float ks[DK];
    int bh = blockIdx.x;
    int b = bh / HEADS, h = bh % HEADS;
    int c = threadIdx.x;
    ks[c] = g_ksum[b * D_MODEL + h * DK + c];
    __syncthreads();

    float w  = convw[c] * INV_SQRT_DK;
    float bb = (float)SEQ * convb[c] * INV_SQRT_DK;

    float logit[DK];
    float mx = -1e30f;
    #pragma unroll
    for (int j = 0; j < DK; j++) {
        logit[j] = fmaf(w, ks[j], bb);
        mx = fmaxf(mx, logit[j]);
    }
    float sum = 0.f;
    #pragma unroll
    for (int j = 0; j < DK; j++) {
        logit[j] = expf(logit[j] - mx);
        sum += logit[j];
    }
    float inv = 1.0f / sum;
    float* Mp = g_M + (size_t)bh * DK * DK;
    #pragma unroll
    for (int j = 0; j < DK; j++)
        Mp[j * DK + c] = logit[j] * inv + (j == c ? 1.0f : 0.0f);
}

// ---------------- weight conversion fp32 -> bf16 hi/lo -------------------------
__global__ void convert_w_kernel(const float* __restrict__ Wv,
                                 const float* __restrict__ Wo)
{
    size_t i = (size_t)blockIdx.x * 256 + threadIdx.x;
    __nv_bfloat16 h, l;
    bsplit(Wv[i], h, l); g_Wvh[i] = h; g_Wvl[i] = l;
    bsplit(Wo[i], h, l); g_Woh[i] = h; g_Wol[i] = l;
}

// ---------------- HMMA bf16-split GEMM -----------------------------------------
// C[128x128] per CTA = A @ W^T ; 3-term split Ah*Bh + Ah*Bl + Al*Bh, fp32 acc.
// grid (4, 512), 256 threads, 8 warps (warp tile 32m x 64n).
// Weight base pointer resolved IN DEVICE CODE from layer index (host must never
// take the address of a __device__ symbol).
#define BK 32
#define NCHK (D_MODEL / BK)   // 16
#define RSTRIDE 80            // bytes per smem row (32 bf16 + 8 pad)

template <int MODE>
__global__ __launch_bounds__(256)
void mma_gemm(int layer, const float* __restrict__ bias)
{
    __shared__ __align__(16) char smAh[128 * RSTRIDE];
    __shared__ __align__(16) char smAl[128 * RSTRIDE];
    __shared__ __align__(16) char smBh[128 * RSTRIDE];
    __shared__ __align__(16) char smBl[128 * RSTRIDE];

    const size_t wofs = (size_t)layer * D_MODEL * D_MODEL;
    const __nv_bfloat16* Wh = ((MODE == 0) ? g_Wvh : g_Woh) + wofs;
    const __nv_bfloat16* Wl = ((MODE == 0) ? g_Wvl : g_Wol) + wofs;
    const float* Asrc = (MODE == 0) ? g_y : g_c;
    float*       Cdst = (MODE == 0) ? g_v : g_x;

    const int tid  = threadIdx.x;
    const int lane = tid & 31;
    const int wid  = tid >> 5;
    const int bn   = blockIdx.x;          // 0..3
    const int bm   = blockIdx.y;          // 0..511
    const int wm   = (wid & 3) * 32;
    const int wn   = (wid >> 2) * 64;

    const size_t arow0 = (size_t)bm * 128;
    const size_t brow0 = (size_t)bn * 128;

    const unsigned uAh = smem_u32(smAh), uAl = smem_u32(smAl);
    const unsigned uBh = smem_u32(smBh), uBl = smem_u32(smBl);

    // per-thread load coordinates (constant across chunks)
    int aRow[4], aFc[4];                  // A: 128 rows x 8 float4-chunks
    #pragma unroll
    for (int i = 0; i < 4; i++) {
        int lin = tid + i * 256;          // 0..1023
        aRow[i] = lin >> 3;
        aFc[i]  = lin & 7;
    }
    int bRow[2], bC[2];                   // B: 128 rows x 4 uint4-chunks
    #pragma unroll
    for (int i = 0; i < 2; i++) {
        int lin = tid + i * 256;          // 0..511
        bRow[i] = lin >> 2;
        bC[i]   = lin & 3;
    }

    float4 rA[4];
    uint4  rBh[2], rBl[2];

    auto ldg_chunk = [&](int k0) {
        #pragma unroll
        for (int i = 0; i < 4; i++)
            rA[i] = *(const float4*)(Asrc + (arow0 + aRow[i]) * D_MODEL + k0 + aFc[i] * 4);
        #pragma unroll
        for (int i = 0; i < 2; i++) {
            size_t gb = (brow0 + bRow[i]) * D_MODEL + k0 + bC[i] * 8;
            rBh[i] = *(const uint4*)(Wh + gb);
            rBl[i] = *(const uint4*)(Wl + gb);
        }
    };

    float acc[2][8][4];
    #pragma unroll
    for (int im = 0; im < 2; im++)
        #pragma unroll
        for (int in = 0; in < 8; in++)
            #pragma unroll
            for (int q = 0; q < 4; q++) acc[im][in][q] = 0.f;

    ldg_chunk(0);

    #pragma unroll 1
    for (int chk = 0; chk < NCHK; chk++) {
        // stage registers -> smem (split A to hi/lo)
        #pragma unroll
        for (int i = 0; i < 4; i++) {
            __nv_bfloat16 h0, h1, h2, h3, l0, l1, l2, l3;
            bsplit(rA[i].x, h0, l0); bsplit(rA[i].y, h1, l1);
            bsplit(rA[i].z, h2, l2); bsplit(rA[i].w, h3, l3);
            unsigned off = (unsigned)(aRow[i] * RSTRIDE + aFc[i] * 8);
            uint2 uh; uh.x = pack2(h0, h1); uh.y = pack2(h2, h3);
            uint2 ul; ul.x = pack2(l0, l1); ul.y = pack2(l2, l3);
            *(uint2*)(smAh + off) = uh;
            *(uint2*)(smAl + off) = ul;
        }
        #pragma unroll
        for (int i = 0; i < 2; i++) {
            unsigned off = (unsigned)(bRow[i] * RSTRIDE + bC[i] * 16);
            *(uint4*)(smBh + off) = rBh[i];
            *(uint4*)(smBl + off) = rBl[i];
        }
        __syncthreads();

        if (chk + 1 < NCHK) ldg_chunk((chk + 1) * BK);   // prefetch next chunk

        #pragma unroll
        for (int ks = 0; ks < 2; ks++) {
            unsigned ah[2][4], al[2][4], bh[4][4], bl[4][4];
            #pragma unroll
            for (int im = 0; im < 2; im++) {
                int row = wm + im * 16 + (lane & 15);
                unsigned cA = (unsigned)(ks * 2 + (lane >> 4));
                unsigned ad = (unsigned)(row * RSTRIDE) + cA * 16u;
                ldsm4(ah[im], uAh + ad);
                ldsm4(al[im], uAl + ad);
            }
            #pragma unroll
            for (int g = 0; g < 4; g++) {
                int row = wn + g * 16 + ((lane >> 4) * 8) + (lane & 7);
                unsigned cB = (unsigned)(ks * 2 + ((lane >> 3) & 1));
                unsigned bd = (unsigned)(row * RSTRIDE) + cB * 16u;
                ldsm4(bh[g], uBh + bd);
                ldsm4(bl[g], uBl + bd);
            }
            #pragma unroll
            for (int im = 0; im < 2; im++) {
                #pragma unroll
                for (int g = 0; g < 4; g++) {
                    mma16816(acc[im][2 * g],     ah[im], &bh[g][0]);
                    mma16816(acc[im][2 * g],     ah[im], &bl[g][0]);
                    mma16816(acc[im][2 * g],     al[im], &bh[g][0]);
                    mma16816(acc[im][2 * g + 1], ah[im], &bh[g][2]);
                    mma16816(acc[im][2 * g + 1], ah[im], &bl[g][2]);
                    mma16816(acc[im][2 * g + 1], al[im], &bh[g][2]);
                }
            }
        }
        __syncthreads();
    }

    // ---------------- epilogue: fragments -> global fp32 ----------------------
    #pragma unroll
    for (int im = 0; im < 2; im++) {
        int r0 = bm * 128 + wm + im * 16 + (lane >> 2);
        #pragma unroll
        for (int in = 0; in < 8; in++) {
            int col = bn * 128 + wn + in * 8 + (lane & 3) * 2;
            float bv0 = bias[col], bv1 = bias[col + 1];
            #pragma unroll
            for (int half = 0; half < 2; half++) {
                int row = r0 + half * 8;
                float v0 = acc[im][in][2 * half + 0] + bv0;
                float v1 = acc[im][in][2 * half + 1] + bv1;
                size_t gi = (size_t)row * D_MODEL + col;
                if (MODE == 0) {
                    *(float2*)(Cdst + gi) = make_float2(v0, v1);
                } else {
                    float2 y = *(const float2*)(g_y + gi);
                    *(float2*)(Cdst + gi) =
                        make_float2(y.x + fmaxf(v0, 0.0f), y.y + fmaxf(v1, 0.0f));
                }
            }
        }
    }
}

// ---------------- per-head out = v @ (scores + I) (R4-proven) ------------------
__global__ __launch_bounds__(256)
void outmm_kernel()
{
    __shared__ __align__(16) float Vs[DK][68];
    __shared__ __align__(16) float Ms[DK][68];

    int bh = blockIdx.y;
    int b = bh >> 3, h = bh & 7;
    int s0 = blockIdx.x * 64;
    int tid = threadIdx.x;

    #pragma unroll
    for (int t = 0; t < 16; t++) {
        int lin = tid + 256 * t;
        int j = lin >> 6, c = lin & 63;
        Ms[j][c] = g_M[((size_t)bh * DK + j) * DK + c];
    }
    #pragma unroll
    for (int t = 0; t < 4; t++) {
        int lin = tid + 256 * t;
        int m = lin >> 4, q = lin & 15;
        float4 f = *(const float4*)(g_v + ((size_t)b * SEQ + s0 + m) * D_MODEL
                                        + h * DK + q * 4);
        Vs[q * 4 + 0][m] = f.x;
        Vs[q * 4 + 1][m] = f.y;
        Vs[q * 4 + 2][m] = f.z;
        Vs[q * 4 + 3][m] = f.w;
    }
    __syncthreads();

    int tm = (tid >> 4) * 4;
    int tc = (tid & 15) * 4;

    ull acc[4][2];
    #pragma unroll
    for (int i = 0; i < 4; i++) { acc[i][0] = 0ull; acc[i][1] = 0ull; }

    #pragma unroll
    for (int j = 0; j < DK; j++) {
        float4 a = *(const float4*)&Vs[j][tm];
        ull b0 = *(const ull*)&Ms[j][tc];
        ull b1 = *(const ull*)&Ms[j][tc + 2];
        float av[4] = {a.x, a.y, a.z, a.w};
        #pragma unroll
        for (int i = 0; i < 4; i++) {
            unsigned au = __float_as_uint(av[i]);
            ull a2;
            asm("mov.b64 %0, {%1, %1};" : "=l"(a2) : "r"(au));
            asm("fma.rn.f32x2 %0, %1, %2, %0;" : "+l"(acc[i][0]) : "l"(a2), "l"(b0));
            asm("fma.rn.f32x2 %0, %1, %2, %0;" : "+l"(acc[i][1]) : "l"(a2), "l"(b1));
        }
    }

    #pragma unroll
    for (int i = 0; i < 4; i++) {
        size_t base = ((size_t)b * SEQ + s0 + tm + i) * D_MODEL + h * DK + tc;
        float2 f0 = u2f2(acc[i][0]);
        float2 f1 = u2f2(acc[i][1]);
        *(float2*)(g_c + base)     = f0;
        *(float2*)(g_c + base + 2) = f1;
    }
}

// ---------------- driver -------------------------------------------------------
extern "C" void kernel_launch(void* const* d_in, const int* in_sizes, int n_in,
                              void* d_out, int out_size)
{
    const float* x    = (const float*)d_in[0];
    const float* Wv   = (const float*)d_in[1];
    const float* bv   = (const float*)d_in[2];
    const float* cw   = (const float*)d_in[3];
    const float* cb   = (const float*)d_in[4];
    const float* Wo   = (const float*)d_in[5];
    const float* bo   = (const float*)d_in[6];
    const float* a1   = (const float*)d_in[7];
    const float* b1   = (const float*)d_in[8];
    const float* a2   = (const float*)d_in[9];
    const float* b2   = (const float*)d_in[10];
    float* out = (float*)d_out;

    // one-shot weight split (deterministic; re-run every call)
    convert_w_kernel<<<(N_LAYERS * D_MODEL * D_MODEL) / 256, 256>>>(Wv, Wo);

    for (int L = 0; L < N_LAYERS; L++) {
        // y = norm1(x)   (fp32)
        norm_kernel<<<ROWS, 128>>>(x, a1 + L * D_MODEL, b1 + L * D_MODEL,
                                   nullptr, (L == 0) ? 0 : 1, 1);
        // ksum = sum_s y
        colsum_kernel<<<BS * 2 * SCHUNKS, 256>>>();
        ksum_reduce_kernel<<<32, 256>>>();
        scores_kernel<<<BS * HEADS, 64>>>(cw + L * DK, cb + L * DK);
        // v = y @ Wv^T + bv   (HMMA bf16 split; weights resolved in-device)
        mma_gemm<0><<<dim3(4, 512), 256>>>(L, bv + L * D_MODEL);
        // concat = per-head v @ (softmax + I)
        outmm_kernel<<<dim3(SEQ / 64, BS * HEADS), 256>>>();
        // z = y + relu(concat @ Wo^T + bo)
        mma_gemm<1><<<dim3(4, 512), 256>>>(L, bo + L * D_MODEL);
        // x = norm2(z)
        norm_kernel<<<ROWS, 128>>>(nullptr, a2 + L * D_MODEL, b2 + L * D_MODEL,
                                   out, 1, (L == N_LAYERS - 1) ? 0 : 2);
    }
}

// round 12
// speedup vs baseline: 2.1529x; 1.1777x over previous
#include <cuda_runtime.h>
#include <cuda_bf16.h>
#include <math.h>

// ---------------- problem constants ----------------
#define D_MODEL 512
#define HEADS   8
#define DK      64
#define N_LAYERS 4
#define BS      16
#define SEQ     4096
#define EPS     1e-6f
#define ROWS    (BS * SEQ)              // 65536
#define INV_SQRT_DK 0.125f
#define SCHUNKS 32

typedef unsigned long long ull;

// ---------------- scratch (device globals) ----------------------------------
__device__ float          g_x [(size_t)ROWS * D_MODEL];   // fp32 layer state
__device__ __nv_bfloat16  g_yh[(size_t)ROWS * D_MODEL];   // norm1 out hi
__device__ __nv_bfloat16  g_yl[(size_t)ROWS * D_MODEL];   // norm1 out lo
__device__ __nv_bfloat16  g_vh[(size_t)ROWS * D_MODEL];
__device__ __nv_bfloat16  g_vl[(size_t)ROWS * D_MODEL];
__device__ __nv_bfloat16  g_ch[(size_t)ROWS * D_MODEL];
__device__ __nv_bfloat16  g_cl[(size_t)ROWS * D_MODEL];
__device__ float g_part[(size_t)BS * SCHUNKS * D_MODEL];
__device__ float g_ksum[BS * D_MODEL];
__device__ float g_M[(size_t)BS * HEADS * DK * DK];
// pre-split bf16 weights (hi/lo), all layers (resolved ONLY in device code)
__device__ __nv_bfloat16 g_Wvh[(size_t)N_LAYERS * D_MODEL * D_MODEL];
__device__ __nv_bfloat16 g_Wvl[(size_t)N_LAYERS * D_MODEL * D_MODEL];
__device__ __nv_bfloat16 g_Woh[(size_t)N_LAYERS * D_MODEL * D_MODEL];
__device__ __nv_bfloat16 g_Wol[(size_t)N_LAYERS * D_MODEL * D_MODEL];

// ---------------- helpers -----------------------------------------------------
__device__ __forceinline__ float2 u2f2(ull u) {
    float2 f;
    f.x = __uint_as_float((unsigned)u);
    f.y = __uint_as_float((unsigned)(u >> 32));
    return f;
}
__device__ __forceinline__ void bsplit(float v, __nv_bfloat16& h, __nv_bfloat16& l) {
    h = __float2bfloat16(v);
    l = __float2bfloat16(v - __bfloat162float(h));
}
__device__ __forceinline__ unsigned pack2(__nv_bfloat16 a, __nv_bfloat16 b) {
    __nv_bfloat162 p = __halves2bfloat162(a, b);
    return *reinterpret_cast<unsigned*>(&p);
}
__device__ __forceinline__ uint2 pack4(__nv_bfloat16 a, __nv_bfloat16 b,
                                       __nv_bfloat16 c, __nv_bfloat16 d) {
    uint2 u;
    u.x = pack2(a, b);
    u.y = pack2(c, d);
    return u;
}
__device__ __forceinline__ unsigned smem_u32(const void* p) {
    unsigned a;
    asm("{ .reg .u64 t; cvta.to.shared.u64 t, %1; cvt.u32.u64 %0, t; }"
        : "=r"(a) : "l"(p));
    return a;
}
__device__ __forceinline__ void mma16816(float* c, const unsigned* a, const unsigned* b) {
    asm volatile(
        "mma.sync.aligned.m16n8k16.row.col.f32.bf16.bf16.f32 "
        "{%0,%1,%2,%3}, {%4,%5,%6,%7}, {%8,%9}, {%0,%1,%2,%3};"
        : "+f"(c[0]), "+f"(c[1]), "+f"(c[2]), "+f"(c[3])
        : "r"(a[0]), "r"(a[1]), "r"(a[2]), "r"(a[3]), "r"(b[0]), "r"(b[1]));
}
__device__ __forceinline__ void ldsm4(unsigned* r, unsigned addr) {
    asm volatile("ldmatrix.sync.aligned.m8n8.x4.shared.b16 {%0,%1,%2,%3}, [%4];"
                 : "=r"(r[0]), "=r"(r[1]), "=r"(r[2]), "=r"(r[3]) : "r"(addr));
}
__device__ __forceinline__ void cp_async16(unsigned dst, const void* src) {
    asm volatile("cp.async.cg.shared.global [%0], [%1], 16;" :: "r"(dst), "l"(src));
}
__device__ __forceinline__ void cp_commit() {
    asm volatile("cp.async.commit_group;" ::: "memory");
}
template <int N>
__device__ __forceinline__ void cp_wait() {
    asm volatile("cp.async.wait_group %0;" :: "n"(N) : "memory");
}

// ---------------- layernorm ----------------------------------------------------
// in_sel: 0 -> ext_in, 1 -> g_x ; out_sel: 0 -> ext_out(fp32), 1 -> g_yh/g_yl, 2 -> g_x
__global__ void norm_kernel(const float* __restrict__ ext_in,
                            const float* __restrict__ alpha,
                            const float* __restrict__ beta,
                            float* __restrict__ ext_out,
                            int in_sel, int out_sel)
{
    const float* in = in_sel ? g_x : ext_in;
    size_t row = blockIdx.x;
    int tid = threadIdx.x;
    const float4 v = ((const float4*)(in + row * D_MODEL))[tid];

    float s  = v.x + v.y + v.z + v.w;
    float ss = v.x * v.x + v.y * v.y + v.z * v.z + v.w * v.w;
    #pragma unroll
    for (int o = 16; o > 0; o >>= 1) {
        s  += __shfl_xor_sync(0xffffffffu, s,  o);
        ss += __shfl_xor_sync(0xffffffffu, ss, o);
    }
    __shared__ float sh[8];
    int wid = tid >> 5, lane = tid & 31;
    if (lane == 0) { sh[wid] = s; sh[4 + wid] = ss; }
    __syncthreads();
    s  = sh[0] + sh[1] + sh[2] + sh[3];
    ss = sh[4] + sh[5] + sh[6] + sh[7];

    float mean = s * (1.0f / D_MODEL);
    float var  = (ss - (float)D_MODEL * mean * mean) * (1.0f / (D_MODEL - 1));
    var = fmaxf(var, 0.0f);
    float r = 1.0f / (sqrtf(var) + EPS);

    float4 a4 = ((const float4*)alpha)[tid];
    float4 b4 = ((const float4*)beta)[tid];
    float o0 = a4.x * (v.x - mean) * r + b4.x;
    float o1 = a4.y * (v.y - mean) * r + b4.y;
    float o2 = a4.z * (v.z - mean) * r + b4.z;
    float o3 = a4.w * (v.w - mean) * r + b4.w;

    if (out_sel == 1) {
        __nv_bfloat16 h0, h1, h2, h3, l0, l1, l2, l3;
        bsplit(o0, h0, l0); bsplit(o1, h1, l1);
        bsplit(o2, h2, l2); bsplit(o3, h3, l3);
        ((uint2*)(g_yh + row * D_MODEL))[tid] = pack4(h0, h1, h2, h3);
        ((uint2*)(g_yl + row * D_MODEL))[tid] = pack4(l0, l1, l2, l3);
    } else {
        float* out = (out_sel == 0) ? ext_out : g_x;
        ((float4*)(out + row * D_MODEL))[tid] = make_float4(o0, o1, o2, o3);
    }
}

// ---------------- column sum of y over seq --------------------------------------
__global__ void colsum_kernel()
{
    int bx = blockIdx.x;
    int b  = bx >> 6;
    int rem = bx & 63;
    int cb = rem >> 5;
    int sc = rem & 31;
    int c  = cb * 256 + threadIdx.x;

    size_t base = ((size_t)b * SEQ + (size_t)sc * 128) * D_MODEL + c;
    float a0 = 0.f, a1 = 0.f;
    #pragma unroll 8
    for (int s = 0; s < 128; s += 2) {
        size_t i0 = base + (size_t)(s + 0) * D_MODEL;
        size_t i1 = base + (size_t)(s + 1) * D_MODEL;
        a0 += __bfloat162float(g_yh[i0]) + __bfloat162float(g_yl[i0]);
        a1 += __bfloat162float(g_yh[i1]) + __bfloat162float(g_yl[i1]);
    }
    g_part[((size_t)b * SCHUNKS + sc) * D_MODEL + c] = a0 + a1;
}

__global__ void ksum_reduce_kernel()
{
    int idx = blockIdx.x * 256 + threadIdx.x;
    int b = idx >> 9;
    int c = idx & (D_MODEL - 1);
    float s = 0.f;
    #pragma unroll
    for (int k = 0; k < SCHUNKS; k++)
        s += g_part[((size_t)b * SCHUNKS + k) * D_MODEL + c];
    g_ksum[idx] = s;
}

// ---------------- scores: M = softmax + I ---------------------------------------
__global__ void scores_kernel(const float* __restrict__ convw,
                              const float* __restrict__ convb)
{
    __shared__ float ks[DK];
    int bh = blockIdx.x;
    int b = bh / HEADS, h = bh % HEADS;
    int c = threadIdx.x;
    ks[c] = g_ksum[b * D_MODEL + h * DK + c];
    __syncthreads();

    float w  = convw[c] * INV_SQRT_DK;
    float bb = (float)SEQ * convb[c] * INV_SQRT_DK;

    float logit[DK];
    float mx = -1e30f;
    #pragma unroll
    for (int j = 0; j < DK; j++) {
        logit[j] = fmaf(w, ks[j], bb);
        mx = fmaxf(mx, logit[j]);
    }
    float sum = 0.f;
    #pragma unroll
    for (int j = 0; j < DK; j++) {
        logit[j] = expf(logit[j] - mx);
        sum += logit[j];
    }
    float inv = 1.0f / sum;
    float* Mp = g_M + (size_t)bh * DK * DK;
    #pragma unroll
    for (int j = 0; j < DK; j++)
        Mp[j * DK + c] = logit[j] * inv + (j == c ? 1.0f : 0.0f);
}

// ---------------- weight conversion fp32 -> bf16 hi/lo --------------------------
__global__ void convert_w_kernel(const float* __restrict__ Wv,
                                 const float* __restrict__ Wo)
{
    size_t i = (size_t)blockIdx.x * 256 + threadIdx.x;
    __nv_bfloat16 h, l;
    bsplit(Wv[i], h, l); g_Wvh[i] = h; g_Wvl[i] = l;
    bsplit(Wo[i], h, l); g_Woh[i] = h; g_Wol[i] = l;
}

// ---------------- HMMA bf16-split GEMM, cp.async double-buffered ----------------
// C[128x128] per CTA = A @ W^T ; 3-term split Ah*Bh + Ah*Bl + Al*Bh, fp32 acc.
// grid (4, 512), 256 threads, 8 warps (warp tile 32m x 64n).
// SMEM: dynamic, 2 stages x 4 tiles (Ah,Al,Bh,Bl) of [128 x 32bf16], 80B rows.
#define BK 32
#define NCHK (D_MODEL / BK)      // 16
#define RSTRIDE 80               // bytes per smem row (64B data + 16B pad)
#define TILE_B (128 * RSTRIDE)   // 10240
#define STAGE_B (4 * TILE_B)     // 40960
#define T_AH 0u
#define T_AL ((unsigned)TILE_B)
#define T_BH ((unsigned)(2 * TILE_B))
#define T_BL ((unsigned)(3 * TILE_B))
#define GEMM_DYN (2 * STAGE_B)   // 81920

template <int MODE>
__global__ __launch_bounds__(256)
void mma_gemm(int layer, const float* __restrict__ bias)
{
    extern __shared__ __align__(16) char dyn[];
    const unsigned dynb = smem_u32(dyn);

    const size_t wofs = (size_t)layer * D_MODEL * D_MODEL;
    const __nv_bfloat16* Wh = ((MODE == 0) ? g_Wvh : g_Woh) + wofs;
    const __nv_bfloat16* Wl = ((MODE == 0) ? g_Wvl : g_Wol) + wofs;
    const __nv_bfloat16* Ah = (MODE == 0) ? g_yh : g_ch;
    const __nv_bfloat16* Al = (MODE == 0) ? g_yl : g_cl;

    const int tid  = threadIdx.x;
    const int lane = tid & 31;
    const int wid  = tid >> 5;
    const int bn   = blockIdx.x;          // 0..3
    const int bm   = blockIdx.y;          // 0..511
    const int wm   = (wid & 3) * 32;
    const int wn   = (wid >> 2) * 64;

    const size_t arow0 = (size_t)bm * 128;
    const size_t brow0 = (size_t)bn * 128;

    // per-thread cp.async coordinates: tile = 128 rows x 4 16B lines
    int ldRow[2], ldC[2];
    #pragma unroll
    for (int i = 0; i < 2; i++) {
        int lin = tid + i * 256;          // 0..511
        ldRow[i] = lin >> 2;
        ldC[i]   = lin & 3;
    }

    auto load_stage = [&](int chk, unsigned sb) {
        int k0 = chk * BK;
        #pragma unroll
        for (int i = 0; i < 2; i++) {
            unsigned so = (unsigned)(ldRow[i] * RSTRIDE + ldC[i] * 16);
            size_t ga = (arow0 + ldRow[i]) * D_MODEL + k0 + ldC[i] * 8;
            size_t gb = (brow0 + ldRow[i]) * D_MODEL + k0 + ldC[i] * 8;
            cp_async16(sb + T_AH + so, Ah + ga);
            cp_async16(sb + T_AL + so, Al + ga);
            cp_async16(sb + T_BH + so, Wh + gb);
            cp_async16(sb + T_BL + so, Wl + gb);
        }
    };

    float acc[2][8][4];
    #pragma unroll
    for (int im = 0; im < 2; im++)
        #pragma unroll
        for (int in = 0; in < 8; in++)
            #pragma unroll
            for (int q = 0; q < 4; q++) acc[im][in][q] = 0.f;

    load_stage(0, dynb);
    cp_commit();
    load_stage(1, dynb + STAGE_B);
    cp_commit();
    cp_wait<1>();
    __syncthreads();

    #pragma unroll 1
    for (int chk = 0; chk < NCHK; chk++) {
        const unsigned sb = dynb + (chk & 1) * STAGE_B;

        #pragma unroll
        for (int ks = 0; ks < 2; ks++) {
            unsigned ah[2][4], al[2][4], bh[4][4], bl[4][4];
            #pragma unroll
            for (int im = 0; im < 2; im++) {
                int row = wm + im * 16 + (lane & 15);
                unsigned cA = (unsigned)(ks * 2 + (lane >> 4));
                unsigned ad = (unsigned)(row * RSTRIDE) + cA * 16u;
                ldsm4(ah[im], sb + T_AH + ad);
                ldsm4(al[im], sb + T_AL + ad);
            }
            #pragma unroll
            for (int g = 0; g < 4; g++) {
                int row = wn + g * 16 + ((lane >> 4) * 8) + (lane & 7);
                unsigned cB = (unsigned)(ks * 2 + ((lane >> 3) & 1));
                unsigned bd = (unsigned)(row * RSTRIDE) + cB * 16u;
                ldsm4(bh[g], sb + T_BH + bd);
                ldsm4(bl[g], sb + T_BL + bd);
            }
            #pragma unroll
            for (int im = 0; im < 2; im++) {
                #pragma unroll
                for (int g = 0; g < 4; g++) {
                    mma16816(acc[im][2 * g],     ah[im], &bh[g][0]);
                    mma16816(acc[im][2 * g],     ah[im], &bl[g][0]);
                    mma16816(acc[im][2 * g],     al[im], &bh[g][0]);
                    mma16816(acc[im][2 * g + 1], ah[im], &bh[g][2]);
                    mma16816(acc[im][2 * g + 1], ah[im], &bl[g][2]);
                    mma16816(acc[im][2 * g + 1], al[im], &bh[g][2]);
                }
            }
        }
        __syncthreads();                      // all reads of stage (chk&1) done
        if (chk + 2 < NCHK) {
            load_stage(chk + 2, sb);          // refill freed stage
            cp_commit();
            cp_wait<1>();                     // stage for chk+1 is complete
        } else {
            cp_wait<0>();
        }
        __syncthreads();
    }

    // ---------------- epilogue: fragments -> global ---------------------------
    #pragma unroll
    for (int im = 0; im < 2; im++) {
        int r0 = bm * 128 + wm + im * 16 + (lane >> 2);
        #pragma unroll
        for (int in = 0; in < 8; in++) {
            int col = bn * 128 + wn + in * 8 + (lane & 3) * 2;
            float bv0 = bias[col], bv1 = bias[col + 1];
            #pragma unroll
            for (int half = 0; half < 2; half++) {
                int row = r0 + half * 8;
                float v0 = acc[im][in][2 * half + 0] + bv0;
                float v1 = acc[im][in][2 * half + 1] + bv1;
                size_t gi = (size_t)row * D_MODEL + col;
                if (MODE == 0) {
                    __nv_bfloat16 h0, h1, l0, l1;
                    bsplit(v0, h0, l0);
                    bsplit(v1, h1, l1);
                    *(unsigned*)(g_vh + gi) = pack2(h0, h1);
                    *(unsigned*)(g_vl + gi) = pack2(l0, l1);
                } else {
                    unsigned ryh = *(const unsigned*)(g_yh + gi);
                    unsigned ryl = *(const unsigned*)(g_yl + gi);
                    float2 yh = __bfloat1622float2(*(__nv_bfloat162*)&ryh);
                    float2 yl = __bfloat1622float2(*(__nv_bfloat162*)&ryl);
                    float o0 = (yh.x + yl.x) + fmaxf(v0, 0.0f);
                    float o1 = (yh.y + yl.y) + fmaxf(v1, 0.0f);
                    *(float2*)(g_x + gi) = make_float2(o0, o1);
                }
            }
        }
    }
}

// ---------------- per-head out = v @ (scores + I) -------------------------------
__global__ __launch_bounds__(256)
void outmm_kernel()
{
    __shared__ __align__(16) float Vs[DK][68];
    __shared__ __align__(16) float Ms[DK][68];

    int bh = blockIdx.y;
    int b = bh >> 3, h = bh & 7;
    int s0 = blockIdx.x * 64;
    int tid = threadIdx.x;

    #pragma unroll
    for (int t = 0; t < 16; t++) {
        int lin = tid + 256 * t;
        int j = lin >> 6, c = lin & 63;
        Ms[j][c] = g_M[((size_t)bh * DK + j) * DK + c];
    }
    #pragma unroll
    for (int t = 0; t < 2; t++) {
        int lin = tid + 256 * t;          // 0..511
        int m = lin >> 3, q = lin & 7;
        size_t gb = ((size_t)b * SEQ + s0 + m) * D_MODEL + h * DK + q * 8;
        uint4 uh = *(const uint4*)(g_vh + gb);
        uint4 ul = *(const uint4*)(g_vl + gb);
        const __nv_bfloat162* hb = (const __nv_bfloat162*)&uh;
        const __nv_bfloat162* lb = (const __nv_bfloat162*)&ul;
        #pragma unroll
        for (int p = 0; p < 4; p++) {
            float2 fh = __bfloat1622float2(hb[p]);
            float2 fl = __bfloat1622float2(lb[p]);
            Vs[q * 8 + 2 * p    ][m] = fh.x + fl.x;
            Vs[q * 8 + 2 * p + 1][m] = fh.y + fl.y;
        }
    }
    __syncthreads();

    int tm = (tid >> 4) * 4;
    int tc = (tid & 15) * 4;

    ull acc[4][2];
    #pragma unroll
    for (int i = 0; i < 4; i++) { acc[i][0] = 0ull; acc[i][1] = 0ull; }

    #pragma unroll
    for (int j = 0; j < DK; j++) {
        float4 a = *(const float4*)&Vs[j][tm];
        ull b0 = *(const ull*)&Ms[j][tc];
        ull b1 = *(const ull*)&Ms[j][tc + 2];
        float av[4] = {a.x, a.y, a.z, a.w};
        #pragma unroll
        for (int i = 0; i < 4; i++) {
            unsigned au = __float_as_uint(av[i]);
            ull a2;
            asm("mov.b64 %0, {%1, %1};" : "=l"(a2) : "r"(au));
            asm("fma.rn.f32x2 %0, %1, %2, %0;" : "+l"(acc[i][0]) : "l"(a2), "l"(b0));
            asm("fma.rn.f32x2 %0, %1, %2, %0;" : "+l"(acc[i][1]) : "l"(a2), "l"(b1));
        }
    }

    #pragma unroll
    for (int i = 0; i < 4; i++) {
        size_t base = ((size_t)b * SEQ + s0 + tm + i) * D_MODEL + h * DK + tc;
        float2 f0 = u2f2(acc[i][0]);
        float2 f1 = u2f2(acc[i][1]);
        __nv_bfloat16 h0, h1, h2, h3, l0, l1, l2, l3;
        bsplit(f0.x, h0, l0); bsplit(f0.y, h1, l1);
        bsplit(f1.x, h2, l2); bsplit(f1.y, h3, l3);
        *(uint2*)(g_ch + base) = pack4(h0, h1, h2, h3);
        *(uint2*)(g_cl + base) = pack4(l0, l1, l2, l3);
    }
}

// ---------------- driver ---------------------------------------------------------
extern "C" void kernel_launch(void* const* d_in, const int* in_sizes, int n_in,
                              void* d_out, int out_size)
{
    const float* x    = (const float*)d_in[0];
    const float* Wv   = (const float*)d_in[1];
    const float* bv   = (const float*)d_in[2];
    const float* cw   = (const float*)d_in[3];
    const float* cb   = (const float*)d_in[4];
    const float* Wo   = (const float*)d_in[5];
    const float* bo   = (const float*)d_in[6];
    const float* a1   = (const float*)d_in[7];
    const float* b1   = (const float*)d_in[8];
    const float* a2   = (const float*)d_in[9];
    const float* b2   = (const float*)d_in[10];
    float* out = (float*)d_out;

    cudaFuncSetAttribute(mma_gemm<0>, cudaFuncAttributeMaxDynamicSharedMemorySize, GEMM_DYN);
    cudaFuncSetAttribute(mma_gemm<1>, cudaFuncAttributeMaxDynamicSharedMemorySize, GEMM_DYN);

    // one-shot weight split (deterministic; re-run every call)
    convert_w_kernel<<<(N_LAYERS * D_MODEL * D_MODEL) / 256, 256>>>(Wv, Wo);

    for (int L = 0; L < N_LAYERS; L++) {
        // y = norm1(x) -> bf16 hi/lo
        norm_kernel<<<ROWS, 128>>>(x, a1 + L * D_MODEL, b1 + L * D_MODEL,
                                   nullptr, (L == 0) ? 0 : 1, 1);
        // ksum = sum_s y
        colsum_kernel<<<BS * 2 * SCHUNKS, 256>>>();
        ksum_reduce_kernel<<<32, 256>>>();
        scores_kernel<<<BS * HEADS, 64>>>(cw + L * DK, cb + L * DK);
        // v = y @ Wv^T + bv   (HMMA bf16 split, cp.async pipeline)
        mma_gemm<0><<<dim3(4, 512), 256, GEMM_DYN>>>(L, bv + L * D_MODEL);
        // concat = per-head v @ (softmax + I)
        outmm_kernel<<<dim3(SEQ / 64, BS * HEADS), 256>>>();
        // z = y + relu(concat @ Wo^T + bo)
        mma_gemm<1><<<dim3(4, 512), 256, GEMM_DYN>>>(L, bo + L * D_MODEL);
        // x = norm2(z)
        norm_kernel<<<ROWS, 128>>>(nullptr, a2 + L * D_MODEL, b2 + L * D_MODEL,
                                   out, 1, (L == N_LAYERS - 1) ? 0 : 2);
    }
}

// round 13
// speedup vs baseline: 2.1611x; 1.0038x over previous
#include <cuda_runtime.h>
#include <cuda_bf16.h>
#include <math.h>

// ---------------- problem constants ----------------
#define D_MODEL 512
#define HEADS   8
#define DK      64
#define N_LAYERS 4
#define BS      16
#define SEQ     4096
#define EPS     1e-6f
#define ROWS    (BS * SEQ)              // 65536
#define INV_SQRT_DK 0.125f
#define SCHUNKS 32

typedef unsigned long long ull;

// ---------------- scratch (device globals) ----------------------------------
__device__ float          g_x [(size_t)ROWS * D_MODEL];   // fp32 layer state
__device__ __nv_bfloat16  g_yh[(size_t)ROWS * D_MODEL];   // norm1 out hi
__device__ __nv_bfloat16  g_yl[(size_t)ROWS * D_MODEL];   // norm1 out lo
__device__ __nv_bfloat16  g_vh[(size_t)ROWS * D_MODEL];
__device__ __nv_bfloat16  g_vl[(size_t)ROWS * D_MODEL];
__device__ __nv_bfloat16  g_ch[(size_t)ROWS * D_MODEL];
__device__ __nv_bfloat16  g_cl[(size_t)ROWS * D_MODEL];
__device__ float g_part[(size_t)BS * SCHUNKS * D_MODEL];
__device__ float g_ksum[BS * D_MODEL];
__device__ float g_M[(size_t)BS * HEADS * DK * DK];
// pre-split bf16 weights (hi/lo), all layers (resolved ONLY in device code)
__device__ __nv_bfloat16 g_Wvh[(size_t)N_LAYERS * D_MODEL * D_MODEL];
__device__ __nv_bfloat16 g_Wvl[(size_t)N_LAYERS * D_MODEL * D_MODEL];
__device__ __nv_bfloat16 g_Woh[(size_t)N_LAYERS * D_MODEL * D_MODEL];
__device__ __nv_bfloat16 g_Wol[(size_t)N_LAYERS * D_MODEL * D_MODEL];

// ---------------- helpers -----------------------------------------------------
__device__ __forceinline__ float2 u2f2(ull u) {
    float2 f;
    f.x = __uint_as_float((unsigned)u);
    f.y = __uint_as_float((unsigned)(u >> 32));
    return f;
}
__device__ __forceinline__ void bsplit(float v, __nv_bfloat16& h, __nv_bfloat16& l) {
    h = __float2bfloat16(v);
    l = __float2bfloat16(v - __bfloat162float(h));
}
__device__ __forceinline__ unsigned pack2(__nv_bfloat16 a, __nv_bfloat16 b) {
    __nv_bfloat162 p = __halves2bfloat162(a, b);
    return *reinterpret_cast<unsigned*>(&p);
}
__device__ __forceinline__ uint2 pack4(__nv_bfloat16 a, __nv_bfloat16 b,
                                       __nv_bfloat16 c, __nv_bfloat16 d) {
    uint2 u;
    u.x = pack2(a, b);
    u.y = pack2(c, d);
    return u;
}
__device__ __forceinline__ unsigned smem_u32(const void* p) {
    unsigned a;
    asm("{ .reg .u64 t; cvta.to.shared.u64 t, %1; cvt.u32.u64 %0, t; }"
        : "=r"(a) : "l"(p));
    return a;
}
__device__ __forceinline__ void mma16816(float* c, const unsigned* a, const unsigned* b) {
    asm volatile(
        "mma.sync.aligned.m16n8k16.row.col.f32.bf16.bf16.f32 "
        "{%0,%1,%2,%3}, {%4,%5,%6,%7}, {%8,%9}, {%0,%1,%2,%3};"
        : "+f"(c[0]), "+f"(c[1]), "+f"(c[2]), "+f"(c[3])
        : "r"(a[0]), "r"(a[1]), "r"(a[2]), "r"(a[3]), "r"(b[0]), "r"(b[1]));
}
__device__ __forceinline__ void ldsm4(unsigned* r, unsigned addr) {
    asm volatile("ldmatrix.sync.aligned.m8n8.x4.shared.b16 {%0,%1,%2,%3}, [%4];"
                 : "=r"(r[0]), "=r"(r[1]), "=r"(r[2]), "=r"(r[3]) : "r"(addr));
}
__device__ __forceinline__ void cp_async16(unsigned dst, const void* src) {
    asm volatile("cp.async.cg.shared.global [%0], [%1], 16;" :: "r"(dst), "l"(src));
}
__device__ __forceinline__ void cp_commit() {
    asm volatile("cp.async.commit_group;" ::: "memory");
}
template <int N>
__device__ __forceinline__ void cp_wait() {
    asm volatile("cp.async.wait_group %0;" :: "n"(N) : "memory");
}

// ---------------- layernorm: warp-per-row, 8 rows per CTA ----------------------
// in_sel: 0 -> ext_in, 1 -> g_x ; out_sel: 0 -> ext_out(fp32), 1 -> g_yh/g_yl, 2 -> g_x
__global__ __launch_bounds__(256)
void norm_kernel(const float* __restrict__ ext_in,
                 const float* __restrict__ alpha,
                 const float* __restrict__ beta,
                 float* __restrict__ ext_out,
                 int in_sel, int out_sel)
{
    const float* in = in_sel ? g_x : ext_in;
    int tid  = threadIdx.x;
    int lane = tid & 31;
    int wrp  = tid >> 5;
    size_t row = (size_t)blockIdx.x * 8 + wrp;

    const float4* rp = (const float4*)(in + row * D_MODEL);
    float4 v[4];
    float s = 0.f, ss = 0.f;
    #pragma unroll
    for (int i = 0; i < 4; i++) {
        v[i] = rp[lane + 32 * i];
        s  += v[i].x + v[i].y + v[i].z + v[i].w;
        ss += v[i].x * v[i].x + v[i].y * v[i].y + v[i].z * v[i].z + v[i].w * v[i].w;
    }
    #pragma unroll
    for (int o = 16; o > 0; o >>= 1) {
        s  += __shfl_xor_sync(0xffffffffu, s,  o);
        ss += __shfl_xor_sync(0xffffffffu, ss, o);
    }

    float mean = s * (1.0f / D_MODEL);
    float var  = (ss - (float)D_MODEL * mean * mean) * (1.0f / (D_MODEL - 1));
    var = fmaxf(var, 0.0f);
    float r = 1.0f / (sqrtf(var) + EPS);

    #pragma unroll
    for (int i = 0; i < 4; i++) {
        int c4 = lane + 32 * i;
        float4 a4 = ((const float4*)alpha)[c4];
        float4 b4 = ((const float4*)beta)[c4];
        float o0 = a4.x * (v[i].x - mean) * r + b4.x;
        float o1 = a4.y * (v[i].y - mean) * r + b4.y;
        float o2 = a4.z * (v[i].z - mean) * r + b4.z;
        float o3 = a4.w * (v[i].w - mean) * r + b4.w;
        if (out_sel == 1) {
            __nv_bfloat16 h0, h1, h2, h3, l0, l1, l2, l3;
            bsplit(o0, h0, l0); bsplit(o1, h1, l1);
            bsplit(o2, h2, l2); bsplit(o3, h3, l3);
            ((uint2*)(g_yh + row * D_MODEL))[c4] = pack4(h0, h1, h2, h3);
            ((uint2*)(g_yl + row * D_MODEL))[c4] = pack4(l0, l1, l2, l3);
        } else {
            float* out = (out_sel == 0) ? ext_out : g_x;
            ((float4*)(out + row * D_MODEL))[c4] = make_float4(o0, o1, o2, o3);
        }
    }
}

// ---------------- column sum of y over seq --------------------------------------
__global__ void colsum_kernel()
{
    int bx = blockIdx.x;
    int b  = bx >> 6;
    int rem = bx & 63;
    int cb = rem >> 5;
    int sc = rem & 31;
    int c  = cb * 256 + threadIdx.x;

    size_t base = ((size_t)b * SEQ + (size_t)sc * 128) * D_MODEL + c;
    float a0 = 0.f, a1 = 0.f;
    #pragma unroll 8
    for (int s = 0; s < 128; s += 2) {
        size_t i0 = base + (size_t)(s + 0) * D_MODEL;
        size_t i1 = base + (size_t)(s + 1) * D_MODEL;
        a0 += __bfloat162float(g_yh[i0]) + __bfloat162float(g_yl[i0]);
        a1 += __bfloat162float(g_yh[i1]) + __bfloat162float(g_yl[i1]);
    }
    g_part[((size_t)b * SCHUNKS + sc) * D_MODEL + c] = a0 + a1;
}

__global__ void ksum_reduce_kernel()
{
    int idx = blockIdx.x * 256 + threadIdx.x;
    int b = idx >> 9;
    int c = idx & (D_MODEL - 1);
    float s = 0.f;
    #pragma unroll
    for (int k = 0; k < SCHUNKS; k++)
        s += g_part[((size_t)b * SCHUNKS + k) * D_MODEL + c];
    g_ksum[idx] = s;
}

// ---------------- scores: M = softmax + I ---------------------------------------
__global__ void scores_kernel(const float* __restrict__ convw,
                              const float* __restrict__ convb)
{
    __shared__ float ks[DK];
    int bh = blockIdx.x;
    int b = bh / HEADS, h = bh % HEADS;
    int c = threadIdx.x;
    ks[c] = g_ksum[b * D_MODEL + h * DK + c];
    __syncthreads();

    float w  = convw[c] * INV_SQRT_DK;
    float bb = (float)SEQ * convb[c] * INV_SQRT_DK;

    float logit[DK];
    float mx = -1e30f;
    #pragma unroll
    for (int j = 0; j < DK; j++) {
        logit[j] = fmaf(w, ks[j], bb);
        mx = fmaxf(mx, logit[j]);
    }
    float sum = 0.f;
    #pragma unroll
    for (int j = 0; j < DK; j++) {
        logit[j] = expf(logit[j] - mx);
        sum += logit[j];
    }
    float inv = 1.0f / sum;
    float* Mp = g_M + (size_t)bh * DK * DK;
    #pragma unroll
    for (int j = 0; j < DK; j++)
        Mp[j * DK + c] = logit[j] * inv + (j == c ? 1.0f : 0.0f);
}

// ---------------- weight conversion fp32 -> bf16 hi/lo --------------------------
__global__ void convert_w_kernel(const float* __restrict__ Wv,
                                 const float* __restrict__ Wo)
{
    size_t i = (size_t)blockIdx.x * 256 + threadIdx.x;
    __nv_bfloat16 h, l;
    bsplit(Wv[i], h, l); g_Wvh[i] = h; g_Wvl[i] = l;
    bsplit(Wo[i], h, l); g_Woh[i] = h; g_Wol[i] = l;
}

// ---------------- HMMA bf16-split GEMM, cp.async double-buffered ----------------
// C[128x128] per CTA = A @ W^T ; 3-term split Ah*Bh + Ah*Bl + Al*Bh, fp32 acc.
// grid (4, 512), 256 threads, 8 warps (warp tile 32m x 64n), 2 CTAs/SM target.
// SMEM: dynamic, 2 stages x 4 tiles (Ah,Al,Bh,Bl) of [128 x 32bf16], 80B rows.
#define BK 32
#define NCHK (D_MODEL / BK)      // 16
#define RSTRIDE 80               // bytes per smem row (64B data + 16B pad)
#define TILE_B (128 * RSTRIDE)   // 10240
#define STAGE_B (4 * TILE_B)     // 40960
#define T_AH 0u
#define T_AL ((unsigned)TILE_B)
#define T_BH ((unsigned)(2 * TILE_B))
#define T_BL ((unsigned)(3 * TILE_B))
#define GEMM_DYN (2 * STAGE_B)   // 81920

template <int MODE>
__global__ __launch_bounds__(256, 2)
void mma_gemm(int layer, const float* __restrict__ bias)
{
    extern __shared__ __align__(16) char dyn[];
    const unsigned dynb = smem_u32(dyn);

    const size_t wofs = (size_t)layer * D_MODEL * D_MODEL;
    const __nv_bfloat16* Wh = ((MODE == 0) ? g_Wvh : g_Woh) + wofs;
    const __nv_bfloat16* Wl = ((MODE == 0) ? g_Wvl : g_Wol) + wofs;
    const __nv_bfloat16* Ah = (MODE == 0) ? g_yh : g_ch;
    const __nv_bfloat16* Al = (MODE == 0) ? g_yl : g_cl;

    const int tid  = threadIdx.x;
    const int lane = tid & 31;
    const int wid  = tid >> 5;
    const int bn   = blockIdx.x;          // 0..3
    const int bm   = blockIdx.y;          // 0..511
    const int wm   = (wid & 3) * 32;
    const int wn   = (wid >> 2) * 64;

    const size_t arow0 = (size_t)bm * 128;
    const size_t brow0 = (size_t)bn * 128;

    // per-thread cp.async coordinates: tile = 128 rows x 4 16B lines
    int ldRow[2], ldC[2];
    #pragma unroll
    for (int i = 0; i < 2; i++) {
        int lin = tid + i * 256;          // 0..511
        ldRow[i] = lin >> 2;
        ldC[i]   = lin & 3;
    }

    auto load_stage = [&](int chk, unsigned sb) {
        int k0 = chk * BK;
        #pragma unroll
        for (int i = 0; i < 2; i++) {
            unsigned so = (unsigned)(ldRow[i] * RSTRIDE + ldC[i] * 16);
            size_t ga = (arow0 + ldRow[i]) * D_MODEL + k0 + ldC[i] * 8;
            size_t gb = (brow0 + ldRow[i]) * D_MODEL + k0 + ldC[i] * 8;
            cp_async16(sb + T_AH + so, Ah + ga);
            cp_async16(sb + T_AL + so, Al + ga);
            cp_async16(sb + T_BH + so, Wh + gb);
            cp_async16(sb + T_BL + so, Wl + gb);
        }
    };

    float acc[2][8][4];
    #pragma unroll
    for (int im = 0; im < 2; im++)
        #pragma unroll
        for (int in = 0; in < 8; in++)
            #pragma unroll
            for (int q = 0; q < 4; q++) acc[im][in][q] = 0.f;

    load_stage(0, dynb);
    cp_commit();
    load_stage(1, dynb + STAGE_B);
    cp_commit();
    cp_wait<1>();
    __syncthreads();

    #pragma unroll 1
    for (int chk = 0; chk < NCHK; chk++) {
        const unsigned sb = dynb + (chk & 1) * STAGE_B;

        #pragma unroll
        for (int ks = 0; ks < 2; ks++) {
            unsigned ah[2][4], al[2][4];
            #pragma unroll
            for (int im = 0; im < 2; im++) {
                int row = wm + im * 16 + (lane & 15);
                unsigned cA = (unsigned)(ks * 2 + (lane >> 4));
                unsigned ad = (unsigned)(row * RSTRIDE) + cA * 16u;
                ldsm4(ah[im], sb + T_AH + ad);
                ldsm4(al[im], sb + T_AL + ad);
            }
            // B fragments loaded per g-group to keep the live set small
            // (launch_bounds(256,2) register budget)
            #pragma unroll
            for (int g = 0; g < 4; g++) {
                unsigned bh[4], bl[4];
                int row = wn + g * 16 + ((lane >> 4) * 8) + (lane & 7);
                unsigned cB = (unsigned)(ks * 2 + ((lane >> 3) & 1));
                unsigned bd = (unsigned)(row * RSTRIDE) + cB * 16u;
                ldsm4(bh, sb + T_BH + bd);
                ldsm4(bl, sb + T_BL + bd);
                #pragma unroll
                for (int im = 0; im < 2; im++) {
                    mma16816(acc[im][2 * g],     ah[im], &bh[0]);
                    mma16816(acc[im][2 * g],     ah[im], &bl[0]);
                    mma16816(acc[im][2 * g],     al[im], &bh[0]);
                    mma16816(acc[im][2 * g + 1], ah[im], &bh[2]);
                    mma16816(acc[im][2 * g + 1], ah[im], &bl[2]);
                    mma16816(acc[im][2 * g + 1], al[im], &bh[2]);
                }
            }
        }
        __syncthreads();                      // all reads of stage (chk&1) done
        if (chk + 2 < NCHK) {
            load_stage(chk + 2, sb);          // refill freed stage
            cp_commit();
            cp_wait<1>();                     // stage for chk+1 is complete
        } else {
            cp_wait<0>();
        }
        __syncthreads();
    }

    // ---------------- epilogue: fragments -> global ---------------------------
    #pragma unroll
    for (int im = 0; im < 2; im++) {
        int r0 = bm * 128 + wm + im * 16 + (lane >> 2);
        #pragma unroll
        for (int in = 0; in < 8; in++) {
            int col = bn * 128 + wn + in * 8 + (lane & 3) * 2;
            float bv0 = bias[col], bv1 = bias[col + 1];
            #pragma unroll
            for (int half = 0; half < 2; half++) {
                int row = r0 + half * 8;
                float v0 = acc[im][in][2 * half + 0] + bv0;
                float v1 = acc[im][in][2 * half + 1] + bv1;
                size_t gi = (size_t)row * D_MODEL + col;
                if (MODE == 0) {
                    __nv_bfloat16 h0, h1, l0, l1;
                    bsplit(v0, h0, l0);
                    bsplit(v1, h1, l1);
                    *(unsigned*)(g_vh + gi) = pack2(h0, h1);
                    *(unsigned*)(g_vl + gi) = pack2(l0, l1);
                } else {
                    unsigned ryh = *(const unsigned*)(g_yh + gi);
                    unsigned ryl = *(const unsigned*)(g_yl + gi);
                    float2 yh = __bfloat1622float2(*(__nv_bfloat162*)&ryh);
                    float2 yl = __bfloat1622float2(*(__nv_bfloat162*)&ryl);
                    float o0 = (yh.x + yl.x) + fmaxf(v0, 0.0f);
                    float o1 = (yh.y + yl.y) + fmaxf(v1, 0.0f);
                    *(float2*)(g_x + gi) = make_float2(o0, o1);
                }
            }
        }
    }
}

// ---------------- per-head out = v @ (scores + I) -------------------------------
__global__ __launch_bounds__(256)
void outmm_kernel()
{
    __shared__ __align__(16) float Vs[DK][68];
    __shared__ __align__(16) float Ms[DK][68];

    int bh = blockIdx.y;
    int b = bh >> 3, h = bh & 7;
    int s0 = blockIdx.x * 64;
    int tid = threadIdx.x;

    #pragma unroll
    for (int t = 0; t < 16; t++) {
        int lin = tid + 256 * t;
        int j = lin >> 6, c = lin & 63;
        Ms[j][c] = g_M[((size_t)bh * DK + j) * DK + c];
    }
    #pragma unroll
    for (int t = 0; t < 2; t++) {
        int lin = tid + 256 * t;          // 0..511
        int m = lin >> 3, q = lin & 7;
        size_t gb = ((size_t)b * SEQ + s0 + m) * D_MODEL + h * DK + q * 8;
        uint4 uh = *(const uint4*)(g_vh + gb);
        uint4 ul = *(const uint4*)(g_vl + gb);
        const __nv_bfloat162* hb = (const __nv_bfloat162*)&uh;
        const __nv_bfloat162* lb = (const __nv_bfloat162*)&ul;
        #pragma unroll
        for (int p = 0; p < 4; p++) {
            float2 fh = __bfloat1622float2(hb[p]);
            float2 fl = __bfloat1622float2(lb[p]);
            Vs[q * 8 + 2 * p    ][m] = fh.x + fl.x;
            Vs[q * 8 + 2 * p + 1][m] = fh.y + fl.y;
        }
    }
    __syncthreads();

    int tm = (tid >> 4) * 4;
    int tc = (tid & 15) * 4;

    ull acc[4][2];
    #pragma unroll
    for (int i = 0; i < 4; i++) { acc[i][0] = 0ull; acc[i][1] = 0ull; }

    #pragma unroll
    for (int j = 0; j < DK; j++) {
        float4 a = *(const float4*)&Vs[j][tm];
        ull b0 = *(const ull*)&Ms[j][tc];
        ull b1 = *(const ull*)&Ms[j][tc + 2];
        float av[4] = {a.x, a.y, a.z, a.w};
        #pragma unroll
        for (int i = 0; i < 4; i++) {
            unsigned au = __float_as_uint(av[i]);
            ull a2;
            asm("mov.b64 %0, {%1, %1};" : "=l"(a2) : "r"(au));
            asm("fma.rn.f32x2 %0, %1, %2, %0;" : "+l"(acc[i][0]) : "l"(a2), "l"(b0));
            asm("fma.rn.f32x2 %0, %1, %2, %0;" : "+l"(acc[i][1]) : "l"(a2), "l"(b1));
        }
    }

    #pragma unroll
    for (int i = 0; i < 4; i++) {
        size_t base = ((size_t)b * SEQ + s0 + tm + i) * D_MODEL + h * DK + tc;
        float2 f0 = u2f2(acc[i][0]);
        float2 f1 = u2f2(acc[i][1]);
        __nv_bfloat16 h0, h1, h2, h3, l0, l1, l2, l3;
        bsplit(f0.x, h0, l0); bsplit(f0.y, h1, l1);
        bsplit(f1.x, h2, l2); bsplit(f1.y, h3, l3);
        *(uint2*)(g_ch + base) = pack4(h0, h1, h2, h3);
        *(uint2*)(g_cl + base) = pack4(l0, l1, l2, l3);
    }
}

// ---------------- driver ---------------------------------------------------------
extern "C" void kernel_launch(void* const* d_in, const int* in_sizes, int n_in,
                              void* d_out, int out_size)
{
    const float* x    = (const float*)d_in[0];
    const float* Wv   = (const float*)d_in[1];
    const float* bv   = (const float*)d_in[2];
    const float* cw   = (const float*)d_in[3];
    const float* cb   = (const float*)d_in[4];
    const float* Wo   = (const float*)d_in[5];
    const float* bo   = (const float*)d_in[6];
    const float* a1   = (const float*)d_in[7];
    const float* b1   = (const float*)d_in[8];
    const float* a2   = (const float*)d_in[9];
    const float* b2   = (const float*)d_in[10];
    float* out = (float*)d_out;

    cudaFuncSetAttribute(mma_gemm<0>, cudaFuncAttributeMaxDynamicSharedMemorySize, GEMM_DYN);
    cudaFuncSetAttribute(mma_gemm<1>, cudaFuncAttributeMaxDynamicSharedMemorySize, GEMM_DYN);

    // one-shot weight split (deterministic; re-run every call)
    convert_w_kernel<<<(N_LAYERS * D_MODEL * D_MODEL) / 256, 256>>>(Wv, Wo);

    for (int L = 0; L < N_LAYERS; L++) {
        // y = norm1(x) -> bf16 hi/lo   (warp-per-row)
        norm_kernel<<<ROWS / 8, 256>>>(x, a1 + L * D_MODEL, b1 + L * D_MODEL,
                                       nullptr, (L == 0) ? 0 : 1, 1);
        // ksum = sum_s y
        colsum_kernel<<<BS * 2 * SCHUNKS, 256>>>();
        ksum_reduce_kernel<<<32, 256>>>();
        scores_kernel<<<BS * HEADS, 64>>>(cw + L * DK, cb + L * DK);
        // v = y @ Wv^T + bv   (HMMA bf16 split, cp.async pipeline)
        mma_gemm<0><<<dim3(4, 512), 256, GEMM_DYN>>>(L, bv + L * D_MODEL);
        // concat = per-head v @ (softmax + I)
        outmm_kernel<<<dim3(SEQ / 64, BS * HEADS), 256>>>();
        // z = y + relu(concat @ Wo^T + bo)
        mma_gemm<1><<<dim3(4, 512), 256, GEMM_DYN>>>(L, bo + L * D_MODEL);
        // x = norm2(z)   (warp-per-row)
        norm_kernel<<<ROWS / 8, 256>>>(nullptr, a2 + L * D_MODEL, b2 + L * D_MODEL,
                                       out, 1, (L == N_LAYERS - 1) ? 0 : 2);
    }
}

// round 14
// speedup vs baseline: 2.6131x; 1.2091x over previous
#include <cuda_runtime.h>
#include <cuda_fp16.h>
#include <math.h>

// ---------------- problem constants ----------------
#define D_MODEL 512
#define HEADS   8
#define DK      64
#define N_LAYERS 4
#define BS      16
#define SEQ     4096
#define EPS     1e-6f
#define ROWS    (BS * SEQ)              // 65536
#define INV_SQRT_DK 0.125f
#define SCHUNKS 32

typedef unsigned long long ull;

// ---------------- scratch (device globals) ----------------------------------
__device__ float  g_x [(size_t)ROWS * D_MODEL];   // fp32 layer state
__device__ __half g_yh[(size_t)ROWS * D_MODEL];   // norm1 out hi (GEMM A)
__device__ __half g_yl[(size_t)ROWS * D_MODEL];   // norm1 out lo (residual/colsum)
__device__ __half g_vh[(size_t)ROWS * D_MODEL];   // v hi
__device__ __half g_vl[(size_t)ROWS * D_MODEL];   // v lo (outmm exactness)
__device__ __half g_c [(size_t)ROWS * D_MODEL];   // concat, single fp16
__device__ float g_part[(size_t)BS * SCHUNKS * D_MODEL];
__device__ float g_ksum[BS * D_MODEL];
__device__ float g_M[(size_t)BS * HEADS * DK * DK];
// pre-split fp16 weights (hi/lo), all layers (resolved ONLY in device code)
__device__ __half g_Wvh[(size_t)N_LAYERS * D_MODEL * D_MODEL];
__device__ __half g_Wvl[(size_t)N_LAYERS * D_MODEL * D_MODEL];
__device__ __half g_Woh[(size_t)N_LAYERS * D_MODEL * D_MODEL];
__device__ __half g_Wol[(size_t)N_LAYERS * D_MODEL * D_MODEL];

// ---------------- helpers -----------------------------------------------------
__device__ __forceinline__ float2 u2f2(ull u) {
    float2 f;
    f.x = __uint_as_float((unsigned)u);
    f.y = __uint_as_float((unsigned)(u >> 32));
    return f;
}
__device__ __forceinline__ void hsplit(float v, __half& h, __half& l) {
    h = __float2half_rn(v);
    l = __float2half_rn(v - __half2float(h));
}
__device__ __forceinline__ unsigned hpack2(__half a, __half b) {
    __half2 p = __halves2half2(a, b);
    return *reinterpret_cast<unsigned*>(&p);
}
__device__ __forceinline__ uint2 hpack4(__half a, __half b, __half c, __half d) {
    uint2 u;
    u.x = hpack2(a, b);
    u.y = hpack2(c, d);
    return u;
}
__device__ __forceinline__ unsigned smem_u32(const void* p) {
    unsigned a;
    asm("{ .reg .u64 t; cvta.to.shared.u64 t, %1; cvt.u32.u64 %0, t; }"
        : "=r"(a) : "l"(p));
    return a;
}
__device__ __forceinline__ void mma16816(float* c, const unsigned* a, const unsigned* b) {
    asm volatile(
        "mma.sync.aligned.m16n8k16.row.col.f32.f16.f16.f32 "
        "{%0,%1,%2,%3}, {%4,%5,%6,%7}, {%8,%9}, {%0,%1,%2,%3};"
        : "+f"(c[0]), "+f"(c[1]), "+f"(c[2]), "+f"(c[3])
        : "r"(a[0]), "r"(a[1]), "r"(a[2]), "r"(a[3]), "r"(b[0]), "r"(b[1]));
}
__device__ __forceinline__ void ldsm4(unsigned* r, unsigned addr) {
    asm volatile("ldmatrix.sync.aligned.m8n8.x4.shared.b16 {%0,%1,%2,%3}, [%4];"
                 : "=r"(r[0]), "=r"(r[1]), "=r"(r[2]), "=r"(r[3]) : "r"(addr));
}
__device__ __forceinline__ void cp_async16(unsigned dst, const void* src) {
    asm volatile("cp.async.cg.shared.global [%0], [%1], 16;" :: "r"(dst), "l"(src));
}
__device__ __forceinline__ void cp_commit() {
    asm volatile("cp.async.commit_group;" ::: "memory");
}
template <int N>
__device__ __forceinline__ void cp_wait() {
    asm volatile("cp.async.wait_group %0;" :: "n"(N) : "memory");
}

// ---------------- layernorm: warp-per-row, 8 rows per CTA ----------------------
// in_sel: 0 -> ext_in, 1 -> g_x ; out_sel: 0 -> ext_out(fp32), 1 -> g_yh/g_yl, 2 -> g_x
__global__ __launch_bounds__(256)
void norm_kernel(const float* __restrict__ ext_in,
                 const float* __restrict__ alpha,
                 const float* __restrict__ beta,
                 float* __restrict__ ext_out,
                 int in_sel, int out_sel)
{
    const float* in = in_sel ? g_x : ext_in;
    int tid  = threadIdx.x;
    int lane = tid & 31;
    int wrp  = tid >> 5;
    size_t row = (size_t)blockIdx.x * 8 + wrp;

    const float4* rp = (const float4*)(in + row * D_MODEL);
    float4 v[4];
    float s = 0.f, ss = 0.f;
    #pragma unroll
    for (int i = 0; i < 4; i++) {
        v[i] = rp[lane + 32 * i];
        s  += v[i].x + v[i].y + v[i].z + v[i].w;
        ss += v[i].x * v[i].x + v[i].y * v[i].y + v[i].z * v[i].z + v[i].w * v[i].w;
    }
    #pragma unroll
    for (int o = 16; o > 0; o >>= 1) {
        s  += __shfl_xor_sync(0xffffffffu, s,  o);
        ss += __shfl_xor_sync(0xffffffffu, ss, o);
    }

    float mean = s * (1.0f / D_MODEL);
    float var  = (ss - (float)D_MODEL * mean * mean) * (1.0f / (D_MODEL - 1));
    var = fmaxf(var, 0.0f);
    float r = 1.0f / (sqrtf(var) + EPS);

    #pragma unroll
    for (int i = 0; i < 4; i++) {
        int c4 = lane + 32 * i;
        float4 a4 = ((const float4*)alpha)[c4];
        float4 b4 = ((const float4*)beta)[c4];
        float o0 = a4.x * (v[i].x - mean) * r + b4.x;
        float o1 = a4.y * (v[i].y - mean) * r + b4.y;
        float o2 = a4.z * (v[i].z - mean) * r + b4.z;
        float o3 = a4.w * (v[i].w - mean) * r + b4.w;
        if (out_sel == 1) {
            __half h0, h1, h2, h3, l0, l1, l2, l3;
            hsplit(o0, h0, l0); hsplit(o1, h1, l1);
            hsplit(o2, h2, l2); hsplit(o3, h3, l3);
            ((uint2*)(g_yh + row * D_MODEL))[c4] = hpack4(h0, h1, h2, h3);
            ((uint2*)(g_yl + row * D_MODEL))[c4] = hpack4(l0, l1, l2, l3);
        } else {
            float* out = (out_sel == 0) ? ext_out : g_x;
            ((float4*)(out + row * D_MODEL))[c4] = make_float4(o0, o1, o2, o3);
        }
    }
}

// ---------------- column sum of y over seq --------------------------------------
__global__ void colsum_kernel()
{
    int bx = blockIdx.x;
    int b  = bx >> 6;
    int rem = bx & 63;
    int cb = rem >> 5;
    int sc = rem & 31;
    int c  = cb * 256 + threadIdx.x;

    size_t base = ((size_t)b * SEQ + (size_t)sc * 128) * D_MODEL + c;
    float a0 = 0.f, a1 = 0.f;
    #pragma unroll 8
    for (int s = 0; s < 128; s += 2) {
        size_t i0 = base + (size_t)(s + 0) * D_MODEL;
        size_t i1 = base + (size_t)(s + 1) * D_MODEL;
        a0 += __half2float(g_yh[i0]) + __half2float(g_yl[i0]);
        a1 += __half2float(g_yh[i1]) + __half2float(g_yl[i1]);
    }
    g_part[((size_t)b * SCHUNKS + sc) * D_MODEL + c] = a0 + a1;
}

__global__ void ksum_reduce_kernel()
{
    int idx = blockIdx.x * 256 + threadIdx.x;
    int b = idx >> 9;
    int c = idx & (D_MODEL - 1);
    float s = 0.f;
    #pragma unroll
    for (int k = 0; k < SCHUNKS; k++)
        s += g_part[((size_t)b * SCHUNKS + k) * D_MODEL + c];
    g_ksum[idx] = s;
}

// ---------------- scores: M = softmax + I ---------------------------------------
__global__ void scores_kernel(const float* __restrict__ convw,
                              const float* __restrict__ convb)
{
    __shared__ float ks[DK];
    int bh = blockIdx.x;
    int b = bh / HEADS, h = bh % HEADS;
    int c = threadIdx.x;
    ks[c] = g_ksum[b * D_MODEL + h * DK + c];
    __syncthreads();

    float w  = convw[c] * INV_SQRT_DK;
    float bb = (float)SEQ * convb[c] * INV_SQRT_DK;

    float logit[DK];
    float mx = -1e30f;
    #pragma unroll
    for (int j = 0; j < DK; j++) {
        logit[j] = fmaf(w, ks[j], bb);
        mx = fmaxf(mx, logit[j]);
    }
    float sum = 0.f;
    #pragma unroll
    for (int j = 0; j < DK; j++) {
        logit[j] = expf(logit[j] - mx);
        sum += logit[j];
    }
    float inv = 1.0f / sum;
    float* Mp = g_M + (size_t)bh * DK * DK;
    #pragma unroll
    for (int j = 0; j < DK; j++)
        Mp[j * DK + c] = logit[j] * inv + (j == c ? 1.0f : 0.0f);
}

// ---------------- weight conversion fp32 -> fp16 hi/lo --------------------------
__global__ void convert_w_kernel(const float* __restrict__ Wv,
                                 const float* __restrict__ Wo)
{
    size_t i = (size_t)blockIdx.x * 256 + threadIdx.x;
    __half h, l;
    hsplit(Wv[i], h, l); g_Wvh[i] = h; g_Wvl[i] = l;
    hsplit(Wo[i], h, l); g_Woh[i] = h; g_Wol[i] = l;
}

// ---------------- HMMA fp16 GEMM, 2-term (A exact-rounded, B split hi/lo) -------
// C[128x128] per CTA = A @ W^T = Ah·Bh + Ah·Bl (exactly Ah·B), fp32 acc.
// grid (4, 512), 256 threads, 8 warps (warp tile 32m x 64n), occ 2.
// SMEM: dynamic, 2 stages x 3 tiles (A, Bh, Bl) of [128 x 32fp16], 80B rows.
#define BK 32
#define NCHK (D_MODEL / BK)      // 16
#define RSTRIDE 80               // bytes per smem row (64B data + 16B pad)
#define TILE_B (128 * RSTRIDE)   // 10240
#define STAGE_B (3 * TILE_B)     // 30720
#define T_A  0u
#define T_BH ((unsigned)TILE_B)
#define T_BL ((unsigned)(2 * TILE_B))
#define GEMM_DYN (2 * STAGE_B)   // 61440

template <int MODE>
__global__ __launch_bounds__(256, 2)
void mma_gemm(int layer, const float* __restrict__ bias)
{
    extern __shared__ __align__(16) char dyn[];
    const unsigned dynb = smem_u32(dyn);

    const size_t wofs = (size_t)layer * D_MODEL * D_MODEL;
    const __half* Wh = ((MODE == 0) ? g_Wvh : g_Woh) + wofs;
    const __half* Wl = ((MODE == 0) ? g_Wvl : g_Wol) + wofs;
    const __half* A  = (MODE == 0) ? g_yh : g_c;

    const int tid  = threadIdx.x;
    const int lane = tid & 31;
    const int wid  = tid >> 5;
    const int bn   = blockIdx.x;          // 0..3
    const int bm   = blockIdx.y;          // 0..511
    const int wm   = (wid & 3) * 32;
    const int wn   = (wid >> 2) * 64;

    const size_t arow0 = (size_t)bm * 128;
    const size_t brow0 = (size_t)bn * 128;

    // per-thread cp.async coordinates: tile = 128 rows x 4 16B lines
    int ldRow[2], ldC[2];
    #pragma unroll
    for (int i = 0; i < 2; i++) {
        int lin = tid + i * 256;          // 0..511
        ldRow[i] = lin >> 2;
        ldC[i]   = lin & 3;
    }

    auto load_stage = [&](int chk, unsigned sb) {
        int k0 = chk * BK;
        #pragma unroll
        for (int i = 0; i < 2; i++) {
            unsigned so = (unsigned)(ldRow[i] * RSTRIDE + ldC[i] * 16);
            size_t ga = (arow0 + ldRow[i]) * D_MODEL + k0 + ldC[i] * 8;
            size_t gb = (brow0 + ldRow[i]) * D_MODEL + k0 + ldC[i] * 8;
            cp_async16(sb + T_A  + so, A  + ga);
            cp_async16(sb + T_BH + so, Wh + gb);
            cp_async16(sb + T_BL + so, Wl + gb);
        }
    };

    float acc[2][8][4];
    #pragma unroll
    for (int im = 0; im < 2; im++)
        #pragma unroll
        for (int in = 0; in < 8; in++)
            #pragma unroll
            for (int q = 0; q < 4; q++) acc[im][in][q] = 0.f;

    load_stage(0, dynb);
    cp_commit();
    load_stage(1, dynb + STAGE_B);
    cp_commit();
    cp_wait<1>();
    __syncthreads();

    #pragma unroll 1
    for (int chk = 0; chk < NCHK; chk++) {
        const unsigned sb = dynb + (chk & 1) * STAGE_B;

        #pragma unroll
        for (int ks = 0; ks < 2; ks++) {
            unsigned ah[2][4];
            #pragma unroll
            for (int im = 0; im < 2; im++) {
                int row = wm + im * 16 + (lane & 15);
                unsigned cA = (unsigned)(ks * 2 + (lane >> 4));
                unsigned ad = (unsigned)(row * RSTRIDE) + cA * 16u;
                ldsm4(ah[im], sb + T_A + ad);
            }
            #pragma unroll
            for (int g = 0; g < 4; g++) {
                unsigned bh[4], bl[4];
                int row = wn + g * 16 + ((lane >> 4) * 8) + (lane & 7);
                unsigned cB = (unsigned)(ks * 2 + ((lane >> 3) & 1));
                unsigned bd = (unsigned)(row * RSTRIDE) + cB * 16u;
                ldsm4(bh, sb + T_BH + bd);
                ldsm4(bl, sb + T_BL + bd);
                #pragma unroll
                for (int im = 0; im < 2; im++) {
                    mma16816(acc[im][2 * g],     ah[im], &bh[0]);
                    mma16816(acc[im][2 * g],     ah[im], &bl[0]);
                    mma16816(acc[im][2 * g + 1], ah[im], &bh[2]);
                    mma16816(acc[im][2 * g + 1], ah[im], &bl[2]);
                }
            }
        }
        __syncthreads();                      // all reads of stage (chk&1) done
        if (chk + 2 < NCHK) {
            load_stage(chk + 2, sb);          // refill freed stage
            cp_commit();
            cp_wait<1>();                     // stage for chk+1 is complete
        } else {
            cp_wait<0>();
        }
        __syncthreads();
    }

    // ---------------- epilogue: fragments -> global ---------------------------
    #pragma unroll
    for (int im = 0; im < 2; im++) {
        int r0 = bm * 128 + wm + im * 16 + (lane >> 2);
        #pragma unroll
        for (int in = 0; in < 8; in++) {
            int col = bn * 128 + wn + in * 8 + (lane & 3) * 2;
            float bv0 = bias[col], bv1 = bias[col + 1];
            #pragma unroll
            for (int half = 0; half < 2; half++) {
                int row = r0 + half * 8;
                float v0 = acc[im][in][2 * half + 0] + bv0;
                float v1 = acc[im][in][2 * half + 1] + bv1;
                size_t gi = (size_t)row * D_MODEL + col;
                if (MODE == 0) {
                    __half h0, h1, l0, l1;
                    hsplit(v0, h0, l0);
                    hsplit(v1, h1, l1);
                    *(unsigned*)(g_vh + gi) = hpack2(h0, h1);
                    *(unsigned*)(g_vl + gi) = hpack2(l0, l1);
                } else {
                    unsigned ryh = *(const unsigned*)(g_yh + gi);
                    unsigned ryl = *(const unsigned*)(g_yl + gi);
                    float2 yh = __half22float2(*(__half2*)&ryh);
                    float2 yl = __half22float2(*(__half2*)&ryl);
                    float o0 = (yh.x + yl.x) + fmaxf(v0, 0.0f);
                    float o1 = (yh.y + yl.y) + fmaxf(v1, 0.0f);
                    *(float2*)(g_x + gi) = make_float2(o0, o1);
                }
            }
        }
    }
}

// ---------------- per-head out = v @ (scores + I) -------------------------------
__global__ __launch_bounds__(256)
void outmm_kernel()
{
    __shared__ __align__(16) float Vs[DK][68];
    __shared__ __align__(16) float Ms[DK][68];

    int bh = blockIdx.y;
    int b = bh >> 3, h = bh & 7;
    int s0 = blockIdx.x * 64;
    int tid = threadIdx.x;

    #pragma unroll
    for (int t = 0; t < 16; t++) {
        int lin = tid + 256 * t;
        int j = lin >> 6, c = lin & 63;
        Ms[j][c] = g_M[((size_t)bh * DK + j) * DK + c];
    }
    #pragma unroll
    for (int t = 0; t < 2; t++) {
        int lin = tid + 256 * t;          // 0..511
        int m = lin >> 3, q = lin & 7;
        size_t gb = ((size_t)b * SEQ + s0 + m) * D_MODEL + h * DK + q * 8;
        uint4 uh = *(const uint4*)(g_vh + gb);
        uint4 ul = *(const uint4*)(g_vl + gb);
        const __half2* hb = (const __half2*)&uh;
        const __half2* lb = (const __half2*)&ul;
        #pragma unroll
        for (int p = 0; p < 4; p++) {
            float2 fh = __half22float2(hb[p]);
            float2 fl = __half22float2(lb[p]);
            Vs[q * 8 + 2 * p    ][m] = fh.x + fl.x;
            Vs[q * 8 + 2 * p + 1][m] = fh.y + fl.y;
        }
    }
    __syncthreads();

    int tm = (tid >> 4) * 4;
    int tc = (tid & 15) * 4;

    ull acc[4][2];
    #pragma unroll
    for (int i = 0; i < 4; i++) { acc[i][0] = 0ull; acc[i][1] = 0ull; }

    #pragma unroll
    for (int j = 0; j < DK; j++) {
        float4 a = *(const float4*)&Vs[j][tm];
        ull b0 = *(const ull*)&Ms[j][tc];
        ull b1 = *(const ull*)&Ms[j][tc + 2];
        float av[4] = {a.x, a.y, a.z, a.w};
        #pragma unroll
        for (int i = 0; i < 4; i++) {
            unsigned au = __float_as_uint(av[i]);
            ull a2;
            asm("mov.b64 %0, {%1, %1};" : "=l"(a2) : "r"(au));
            asm("fma.rn.f32x2 %0, %1, %2, %0;" : "+l"(acc[i][0]) : "l"(a2), "l"(b0));
            asm("fma.rn.f32x2 %0, %1, %2, %0;" : "+l"(acc[i][1]) : "l"(a2), "l"(b1));
        }
    }

    #pragma unroll
    for (int i = 0; i < 4; i++) {
        size_t base = ((size_t)b * SEQ + s0 + tm + i) * D_MODEL + h * DK + tc;
        float2 f0 = u2f2(acc[i][0]);
        float2 f1 = u2f2(acc[i][1]);
        // c: single fp16 (GEMM1 input only; rounding is the budgeted A-error)
        __half c0 = __float2half_rn(f0.x);
        __half c1 = __float2half_rn(f0.y);
        __half c2 = __float2half_rn(f1.x);
        __half c3 = __float2half_rn(f1.y);
        *(uint2*)(g_c + base) = hpack4(c0, c1, c2, c3);
    }
}

// ---------------- driver ---------------------------------------------------------
extern "C" void kernel_launch(void* const* d_in, const int* in_sizes, int n_in,
                              void* d_out, int out_size)
{
    const float* x    = (const float*)d_in[0];
    const float* Wv   = (const float*)d_in[1];
    const float* bv   = (const float*)d_in[2];
    const float* cw   = (const float*)d_in[3];
    const float* cb   = (const float*)d_in[4];
    const float* Wo   = (const float*)d_in[5];
    const float* bo   = (const float*)d_in[6];
    const float* a1   = (const float*)d_in[7];
    const float* b1   = (const float*)d_in[8];
    const float* a2   = (const float*)d_in[9];
    const float* b2   = (const float*)d_in[10];
    float* out = (float*)d_out;

    cudaFuncSetAttribute(mma_gemm<0>, cudaFuncAttributeMaxDynamicSharedMemorySize, GEMM_DYN);
    cudaFuncSetAttribute(mma_gemm<1>, cudaFuncAttributeMaxDynamicSharedMemorySize, GEMM_DYN);

    // one-shot weight split (deterministic; re-run every call)
    convert_w_kernel<<<(N_LAYERS * D_MODEL * D_MODEL) / 256, 256>>>(Wv, Wo);

    for (int L = 0; L < N_LAYERS; L++) {
        // y = norm1(x) -> fp16 hi/lo   (warp-per-row)
        norm_kernel<<<ROWS / 8, 256>>>(x, a1 + L * D_MODEL, b1 + L * D_MODEL,
                                       nullptr, (L == 0) ? 0 : 1, 1);
        // ksum = sum_s y
        colsum_kernel<<<BS * 2 * SCHUNKS, 256>>>();
        ksum_reduce_kernel<<<32, 256>>>();
        scores_kernel<<<BS * HEADS, 64>>>(cw + L * DK, cb + L * DK);
        // v = y @ Wv^T + bv   (fp16 2-term HMMA)
        mma_gemm<0><<<dim3(4, 512), 256, GEMM_DYN>>>(L, bv + L * D_MODEL);
        // concat = per-head v @ (softmax + I)
        outmm_kernel<<<dim3(SEQ / 64, BS * HEADS), 256>>>();
        // z = y + relu(concat @ Wo^T + bo)
        mma_gemm<1><<<dim3(4, 512), 256, GEMM_DYN>>>(L, bo + L * D_MODEL);
        // x = norm2(z)   (warp-per-row)
        norm_kernel<<<ROWS / 8, 256>>>(nullptr, a2 + L * D_MODEL, b2 + L * D_MODEL,
                                       out, 1, (L == N_LAYERS - 1) ? 0 : 2);
    }
}

// round 15
// speedup vs baseline: 2.6547x; 1.0159x over previous
#include <cuda_runtime.h>
#include <cuda_fp16.h>
#include <math.h>

// ---------------- problem constants ----------------
#define D_MODEL 512
#define HEADS   8
#define DK      64
#define N_LAYERS 4
#define BS      16
#define SEQ     4096
#define EPS     1e-6f
#define ROWS    (BS * SEQ)              // 65536
#define INV_SQRT_DK 0.125f
#define SCHUNKS 32

typedef unsigned long long ull;

// ---------------- scratch (device globals; device-code access ONLY) ----------
__device__ float  g_x [(size_t)ROWS * D_MODEL];   // z buffer (GEMM1 out, fp32)
__device__ __half g_yh[(size_t)ROWS * D_MODEL];   // norm1 out hi
__device__ __half g_yl[(size_t)ROWS * D_MODEL];   // norm1 out lo (exactness)
__device__ __half g_v [(size_t)ROWS * D_MODEL];   // v projection, single fp16
__device__ float g_part[(size_t)BS * SCHUNKS * D_MODEL];
__device__ float g_ksum[BS * D_MODEL];
__device__ float g_M[(size_t)BS * HEADS * DK * DK];          // scores + I
// fused per-batch weights W~_b = blockdiag(M_b) . Wo^T   [16][512][512]
__device__ __half g_Wth[(size_t)BS * D_MODEL * D_MODEL];
__device__ __half g_Wtl[(size_t)BS * D_MODEL * D_MODEL];
// pre-split fp16 Wv (hi/lo), all layers
__device__ __half g_Wvh[(size_t)N_LAYERS * D_MODEL * D_MODEL];
__device__ __half g_Wvl[(size_t)N_LAYERS * D_MODEL * D_MODEL];

// ---------------- helpers -----------------------------------------------------
__device__ __forceinline__ void hsplit(float v, __half& h, __half& l) {
    h = __float2half_rn(v);
    l = __float2half_rn(v - __half2float(h));
}
__device__ __forceinline__ unsigned hpack2(__half a, __half b) {
    __half2 p = __halves2half2(a, b);
    return *reinterpret_cast<unsigned*>(&p);
}
__device__ __forceinline__ uint2 hpack4(__half a, __half b, __half c, __half d) {
    uint2 u;
    u.x = hpack2(a, b);
    u.y = hpack2(c, d);
    return u;
}
__device__ __forceinline__ unsigned smem_u32(const void* p) {
    unsigned a;
    asm("{ .reg .u64 t; cvta.to.shared.u64 t, %1; cvt.u32.u64 %0, t; }"
        : "=r"(a) : "l"(p));
    return a;
}
__device__ __forceinline__ void mma16816(float* c, const unsigned* a, const unsigned* b) {
    asm volatile(
        "mma.sync.aligned.m16n8k16.row.col.f32.f16.f16.f32 "
        "{%0,%1,%2,%3}, {%4,%5,%6,%7}, {%8,%9}, {%0,%1,%2,%3};"
        : "+f"(c[0]), "+f"(c[1]), "+f"(c[2]), "+f"(c[3])
        : "r"(a[0]), "r"(a[1]), "r"(a[2]), "r"(a[3]), "r"(b[0]), "r"(b[1]));
}
__device__ __forceinline__ void ldsm4(unsigned* r, unsigned addr) {
    asm volatile("ldmatrix.sync.aligned.m8n8.x4.shared.b16 {%0,%1,%2,%3}, [%4];"
                 : "=r"(r[0]), "=r"(r[1]), "=r"(r[2]), "=r"(r[3]) : "r"(addr));
}
__device__ __forceinline__ void cp_async16(unsigned dst, const void* src) {
    asm volatile("cp.async.cg.shared.global [%0], [%1], 16;" :: "r"(dst), "l"(src));
}
__device__ __forceinline__ void cp_commit() {
    asm volatile("cp.async.commit_group;" ::: "memory");
}
template <int N>
__device__ __forceinline__ void cp_wait() {
    asm volatile("cp.async.wait_group %0;" :: "n"(N) : "memory");
}

// warp-level mean/invstd of 128 values held as 4x float4 per lane
__device__ __forceinline__ void row_stats(const float4* v, float& mean, float& r) {
    float s = 0.f, ss = 0.f;
    #pragma unroll
    for (int i = 0; i < 4; i++) {
        s  += v[i].x + v[i].y + v[i].z + v[i].w;
        ss += v[i].x * v[i].x + v[i].y * v[i].y + v[i].z * v[i].z + v[i].w * v[i].w;
    }
    #pragma unroll
    for (int o = 16; o > 0; o >>= 1) {
        s  += __shfl_xor_sync(0xffffffffu, s,  o);
        ss += __shfl_xor_sync(0xffffffffu, ss, o);
    }
    mean = s * (1.0f / D_MODEL);
    float var = (ss - (float)D_MODEL * mean * mean) * (1.0f / (D_MODEL - 1));
    var = fmaxf(var, 0.0f);
    r = 1.0f / (sqrtf(var) + EPS);
}

// ---------------- norm kernels (warp-per-row, 8 rows/CTA) ----------------------
// first layer: y = norm(ext_x) -> yh/yl
__global__ __launch_bounds__(256)
void norm_first_kernel(const float* __restrict__ ext_in,
                       const float* __restrict__ alpha,
                       const float* __restrict__ beta)
{
    int tid = threadIdx.x, lane = tid & 31, wrp = tid >> 5;
    size_t row = (size_t)blockIdx.x * 8 + wrp;
    const float4* rp = (const float4*)(ext_in + row * D_MODEL);
    float4 v[4];
    #pragma unroll
    for (int i = 0; i < 4; i++) v[i] = rp[lane + 32 * i];
    float mean, r;
    row_stats(v, mean, r);
    #pragma unroll
    for (int i = 0; i < 4; i++) {
        int c4 = lane + 32 * i;
        float4 a4 = ((const float4*)alpha)[c4];
        float4 b4 = ((const float4*)beta)[c4];
        __half h0, h1, h2, h3, l0, l1, l2, l3;
        hsplit(a4.x * (v[i].x - mean) * r + b4.x, h0, l0);
        hsplit(a4.y * (v[i].y - mean) * r + b4.y, h1, l1);
        hsplit(a4.z * (v[i].z - mean) * r + b4.z, h2, l2);
        hsplit(a4.w * (v[i].w - mean) * r + b4.w, h3, l3);
        ((uint2*)(g_yh + row * D_MODEL))[c4] = hpack4(h0, h1, h2, h3);
        ((uint2*)(g_yl + row * D_MODEL))[c4] = hpack4(l0, l1, l2, l3);
    }
}

// mid layers: t = norm2(z); y = norm1(t) -> yh/yl   (z = g_x)
__global__ __launch_bounds__(256)
void norm_fused_kernel(const float* __restrict__ a2, const float* __restrict__ b2,
                       const float* __restrict__ a1, const float* __restrict__ b1)
{
    int tid = threadIdx.x, lane = tid & 31, wrp = tid >> 5;
    size_t row = (size_t)blockIdx.x * 8 + wrp;
    const float4* rp = (const float4*)(g_x + row * D_MODEL);
    float4 v[4];
    #pragma unroll
    for (int i = 0; i < 4; i++) v[i] = rp[lane + 32 * i];
    float mean, r;
    row_stats(v, mean, r);
    // t = a2*(z-m)/s + b2
    #pragma unroll
    for (int i = 0; i < 4; i++) {
        int c4 = lane + 32 * i;
        float4 a4 = ((const float4*)a2)[c4];
        float4 b4 = ((const float4*)b2)[c4];
        v[i].x = a4.x * (v[i].x - mean) * r + b4.x;
        v[i].y = a4.y * (v[i].y - mean) * r + b4.y;
        v[i].z = a4.z * (v[i].z - mean) * r + b4.z;
        v[i].w = a4.w * (v[i].w - mean) * r + b4.w;
    }
    row_stats(v, mean, r);
    #pragma unroll
    for (int i = 0; i < 4; i++) {
        int c4 = lane + 32 * i;
        float4 a4 = ((const float4*)a1)[c4];
        float4 b4 = ((const float4*)b1)[c4];
        __half h0, h1, h2, h3, l0, l1, l2, l3;
        hsplit(a4.x * (v[i].x - mean) * r + b4.x, h0, l0);
        hsplit(a4.y * (v[i].y - mean) * r + b4.y, h1, l1);
        hsplit(a4.z * (v[i].z - mean) * r + b4.z, h2, l2);
        hsplit(a4.w * (v[i].w - mean) * r + b4.w, h3, l3);
        ((uint2*)(g_yh + row * D_MODEL))[c4] = hpack4(h0, h1, h2, h3);
        ((uint2*)(g_yl + row * D_MODEL))[c4] = hpack4(l0, l1, l2, l3);
    }
}

// last layer: out = norm2(z)  (fp32)
__global__ __launch_bounds__(256)
void norm_last_kernel(const float* __restrict__ alpha,
                      const float* __restrict__ beta,
                      float* __restrict__ out)
{
    int tid = threadIdx.x, lane = tid & 31, wrp = tid >> 5;
    size_t row = (size_t)blockIdx.x * 8 + wrp;
    const float4* rp = (const float4*)(g_x + row * D_MODEL);
    float4 v[4];
    #pragma unroll
    for (int i = 0; i < 4; i++) v[i] = rp[lane + 32 * i];
    float mean, r;
    row_stats(v, mean, r);
    #pragma unroll
    for (int i = 0; i < 4; i++) {
        int c4 = lane + 32 * i;
        float4 a4 = ((const float4*)alpha)[c4];
        float4 b4 = ((const float4*)beta)[c4];
        float4 o4;
        o4.x = a4.x * (v[i].x - mean) * r + b4.x;
        o4.y = a4.y * (v[i].y - mean) * r + b4.y;
        o4.z = a4.z * (v[i].z - mean) * r + b4.z;
        o4.w = a4.w * (v[i].w - mean) * r + b4.w;
        ((float4*)(out + row * D_MODEL))[c4] = o4;
    }
}

// ---------------- column sum of y over seq (exact: yh+yl) ----------------------
__global__ void colsum_kernel()
{
    int bx = blockIdx.x;
    int b  = bx >> 6;
    int rem = bx & 63;
    int cb = rem >> 5;
    int sc = rem & 31;
    int c  = cb * 256 + threadIdx.x;

    size_t base = ((size_t)b * SEQ + (size_t)sc * 128) * D_MODEL + c;
    float a0 = 0.f, a1 = 0.f;
    #pragma unroll 8
    for (int s = 0; s < 128; s += 2) {
        size_t i0 = base + (size_t)(s + 0) * D_MODEL;
        size_t i1 = base + (size_t)(s + 1) * D_MODEL;
        a0 += __half2float(g_yh[i0]) + __half2float(g_yl[i0]);
        a1 += __half2float(g_yh[i1]) + __half2float(g_yl[i1]);
    }
    g_part[((size_t)b * SCHUNKS + sc) * D_MODEL + c] = a0 + a1;
}

__global__ void ksum_reduce_kernel()
{
    int idx = blockIdx.x * 256 + threadIdx.x;
    int b = idx >> 9;
    int c = idx & (D_MODEL - 1);
    float s = 0.f;
    #pragma unroll
    for (int k = 0; k < SCHUNKS; k++)
        s += g_part[((size_t)b * SCHUNKS + k) * D_MODEL + c];
    g_ksum[idx] = s;
}

// ---------------- scores: M = softmax + I ---------------------------------------
__global__ void scores_kernel(const float* __restrict__ convw,
                              const float* __restrict__ convb)
{
    __shared__ float ks[DK];
    int bh = blockIdx.x;
    int b = bh / HEADS, h = bh % HEADS;
    int c = threadIdx.x;
    ks[c] = g_ksum[b * D_MODEL + h * DK + c];
    __syncthreads();

    float w  = convw[c] * INV_SQRT_DK;
    float bb = (float)SEQ * convb[c] * INV_SQRT_DK;

    float logit[DK];
    float mx = -1e30f;
    #pragma unroll
    for (int j = 0; j < DK; j++) {
        logit[j] = fmaf(w, ks[j], bb);
        mx = fmaxf(mx, logit[j]);
    }
    float sum = 0.f;
    #pragma unroll
    for (int j = 0; j < DK; j++) {
        logit[j] = expf(logit[j] - mx);
        sum += logit[j];
    }
    float inv = 1.0f / sum;
    float* Mp = g_M + (size_t)bh * DK * DK;
    #pragma unroll
    for (int j = 0; j < DK; j++)
        Mp[j * DK + c] = logit[j] * inv + (j == c ? 1.0f : 0.0f);
}

// ---------------- W~ build: W~_b[o, h*64+j] = sum_c M_bh[j][c] * Wo[o, h*64+c] --
// grid = BS*HEADS = 128 blocks, 256 threads.
__global__ __launch_bounds__(256)
void make_wt_kernel(const float* __restrict__ Wo)
{
    __shared__ float Ms[DK][DK + 1];
    int bh = blockIdx.x;
    int b = bh >> 3, h = bh & 7;
    int tid = threadIdx.x;

    #pragma unroll
    for (int t = 0; t < 16; t++) {
        int lin = tid + 256 * t;
        Ms[lin >> 6][lin & 63] = g_M[(size_t)bh * DK * DK + lin];
    }
    __syncthreads();

    int j  = tid & 63;
    int og = tid >> 6;                 // 0..3
    #pragma unroll 1
    for (int ob = 0; ob < 8; ob++) {
        #pragma unroll 1
        for (int i = 0; i < 16; i++) {
            int o = ob * 64 + og * 16 + i;
            const float4* wrow = (const float4*)(Wo + (size_t)o * D_MODEL + h * DK);
            float s = 0.f;
            #pragma unroll
            for (int c4 = 0; c4 < 16; c4++) {
                float4 w4 = wrow[c4];
                s += w4.x * Ms[j][c4 * 4 + 0] + w4.y * Ms[j][c4 * 4 + 1]
                   + w4.z * Ms[j][c4 * 4 + 2] + w4.w * Ms[j][c4 * 4 + 3];
            }
            __half hh, hl;
            hsplit(s, hh, hl);
            size_t wi = ((size_t)b * D_MODEL + o) * D_MODEL + h * DK + j;
            g_Wth[wi] = hh;
            g_Wtl[wi] = hl;
        }
    }
}

// ---------------- weight conversion fp32 -> fp16 hi/lo (Wv only) ----------------
__global__ void convert_w_kernel(const float* __restrict__ Wv)
{
    size_t i = (size_t)blockIdx.x * 256 + threadIdx.x;
    __half h, l;
    hsplit(Wv[i], h, l);
    g_Wvh[i] = h;
    g_Wvl[i] = l;
}

// ---------------- GEMM shared geometry -------------------------------------------
#define BK 32
#define NCHK (D_MODEL / BK)      // 16
#define RSTRIDE 80               // bytes per smem row (64B data + 16B pad)
#define TILE_B (128 * RSTRIDE)   // 10240

// ---------------- GEMM0: v = y @ Wv^T + bv  (3-term: A exact hi/lo) -------------
// stage = 4 tiles (Ah, Al, Bh, Bl) = 40960 B; 2 stages = 81920.
#define A3_T_AH 0u
#define A3_T_AL ((unsigned)TILE_B)
#define A3_T_BH ((unsigned)(2 * TILE_B))
#define A3_T_BL ((unsigned)(3 * TILE_B))
#define A3_STAGE (4 * TILE_B)
#define A3_DYN (2 * A3_STAGE)

__global__ __launch_bounds__(256)
void gemm_a3_kernel(int layer, const float* __restrict__ bias)
{
    extern __shared__ __align__(16) char dyn[];
    const unsigned dynb = smem_u32(dyn);

    const size_t wofs = (size_t)layer * D_MODEL * D_MODEL;
    const __half* Wh = g_Wvh + wofs;
    const __half* Wl = g_Wvl + wofs;

    const int tid  = threadIdx.x;
    const int lane = tid & 31;
    const int wid  = tid >> 5;
    const int bn   = blockIdx.x;          // 0..3
    const int bm   = blockIdx.y;          // 0..511
    const int wm   = (wid & 3) * 32;
    const int wn   = (wid >> 2) * 64;

    const size_t arow0 = (size_t)bm * 128;
    const size_t brow0 = (size_t)bn * 128;

    int ldRow[2], ldC[2];
    #pragma unroll
    for (int i = 0; i < 2; i++) {
        int lin = tid + i * 256;
        ldRow[i] = lin >> 2;
        ldC[i]   = lin & 3;
    }

    auto load_stage = [&](int chk, unsigned sb) {
        int k0 = chk * BK;
        #pragma unroll
        for (int i = 0; i < 2; i++) {
            unsigned so = (unsigned)(ldRow[i] * RSTRIDE + ldC[i] * 16);
            size_t ga = (arow0 + ldRow[i]) * D_MODEL + k0 + ldC[i] * 8;
            size_t gb = (brow0 + ldRow[i]) * D_MODEL + k0 + ldC[i] * 8;
            cp_async16(sb + A3_T_AH + so, g_yh + ga);
            cp_async16(sb + A3_T_AL + so, g_yl + ga);
            cp_async16(sb + A3_T_BH + so, Wh + gb);
            cp_async16(sb + A3_T_BL + so, Wl + gb);
        }
    };

    float acc[2][8][4];
    #pragma unroll
    for (int im = 0; im < 2; im++)
        #pragma unroll
        for (int in = 0; in < 8; in++)
            #pragma unroll
            for (int q = 0; q < 4; q++) acc[im][in][q] = 0.f;

    load_stage(0, dynb);
    cp_commit();
    load_stage(1, dynb + A3_STAGE);
    cp_commit();
    cp_wait<1>();
    __syncthreads();

    #pragma unroll 1
    for (int chk = 0; chk < NCHK; chk++) {
        const unsigned sb = dynb + (chk & 1) * A3_STAGE;

        #pragma unroll
        for (int ks = 0; ks < 2; ks++) {
            unsigned ah[2][4], al[2][4];
            #pragma unroll
            for (int im = 0; im < 2; im++) {
                int row = wm + im * 16 + (lane & 15);
                unsigned cA = (unsigned)(ks * 2 + (lane >> 4));
                unsigned ad = (unsigned)(row * RSTRIDE) + cA * 16u;
                ldsm4(ah[im], sb + A3_T_AH + ad);
                ldsm4(al[im], sb + A3_T_AL + ad);
            }
            #pragma unroll
            for (int g = 0; g < 4; g++) {
                unsigned bh[4], bl[4];
                int row = wn + g * 16 + ((lane >> 4) * 8) + (lane & 7);
                unsigned cB = (unsigned)(ks * 2 + ((lane >> 3) & 1));
                unsigned bd = (unsigned)(row * RSTRIDE) + cB * 16u;
                ldsm4(bh, sb + A3_T_BH + bd);
                ldsm4(bl, sb + A3_T_BL + bd);
                #pragma unroll
                for (int im = 0; im < 2; im++) {
                    mma16816(acc[im][2 * g],     ah[im], &bh[0]);
                    mma16816(acc[im][2 * g],     ah[im], &bl[0]);
                    mma16816(acc[im][2 * g],     al[im], &bh[0]);
                    mma16816(acc[im][2 * g + 1], ah[im], &bh[2]);
                    mma16816(acc[im][2 * g + 1], ah[im], &bl[2]);
                    mma16816(acc[im][2 * g + 1], al[im], &bh[2]);
                }
            }
        }
        __syncthreads();
        if (chk + 2 < NCHK) {
            load_stage(chk + 2, sb);
            cp_commit();
            cp_wait<1>();
        } else {
            cp_wait<0>();
        }
        __syncthreads();
    }

    // epilogue: v = acc + bias -> single fp16
    #pragma unroll
    for (int im = 0; im < 2; im++) {
        int r0 = bm * 128 + wm + im * 16 + (lane >> 2);
        #pragma unroll
        for (int in = 0; in < 8; in++) {
            int col = bn * 128 + wn + in * 8 + (lane & 3) * 2;
            float bv0 = bias[col], bv1 = bias[col + 1];
            #pragma unroll
            for (int half = 0; half < 2; half++) {
                int row = r0 + half * 8;
                float v0 = acc[im][in][2 * half + 0] + bv0;
                float v1 = acc[im][in][2 * half + 1] + bv1;
                size_t gi = (size_t)row * D_MODEL + col;
                *(unsigned*)(g_v + gi) =
                    hpack2(__float2half_rn(v0), __float2half_rn(v1));
            }
        }
    }
}

// ---------------- GEMM1: z = y + relu(v @ W~_b^T + bo)  (2-term, B=W~ hi/lo) ----
#define B2_T_A  0u
#define B2_T_BH ((unsigned)TILE_B)
#define B2_T_BL ((unsigned)(2 * TILE_B))
#define B2_STAGE (3 * TILE_B)
#define B2_DYN (2 * B2_STAGE)

__global__ __launch_bounds__(256)
void gemm_b2_kernel(const float* __restrict__ bias)
{
    extern __shared__ __align__(16) char dyn[];
    const unsigned dynb = smem_u32(dyn);

    const int tid  = threadIdx.x;
    const int lane = tid & 31;
    const int wid  = tid >> 5;
    const int bn   = blockIdx.x;          // 0..3
    const int bm   = blockIdx.y;          // 0..511
    const int wm   = (wid & 3) * 32;
    const int wn   = (wid >> 2) * 64;

    const int batch = bm >> 5;            // 32 row-blocks per batch
    const __half* Wh = g_Wth + (size_t)batch * D_MODEL * D_MODEL;
    const __half* Wl = g_Wtl + (size_t)batch * D_MODEL * D_MODEL;

    const size_t arow0 = (size_t)bm * 128;
    const size_t brow0 = (size_t)bn * 128;

    int ldRow[2], ldC[2];
    #pragma unroll
    for (int i = 0; i < 2; i++) {
        int lin = tid + i * 256;
        ldRow[i] = lin >> 2;
        ldC[i]   = lin & 3;
    }

    auto load_stage = [&](int chk, unsigned sb) {
        int k0 = chk * BK;
        #pragma unroll
        for (int i = 0; i < 2; i++) {
            unsigned so = (unsigned)(ldRow[i] * RSTRIDE + ldC[i] * 16);
            size_t ga = (arow0 + ldRow[i]) * D_MODEL + k0 + ldC[i] * 8;
            size_t gb = (brow0 + ldRow[i]) * D_MODEL + k0 + ldC[i] * 8;
            cp_async16(sb + B2_T_A  + so, g_v + ga);
            cp_async16(sb + B2_T_BH + so, Wh + gb);
            cp_async16(sb + B2_T_BL + so, Wl + gb);
        }
    };

    float acc[2][8][4];
    #pragma unroll
    for (int im = 0; im < 2; im++)
        #pragma unroll
        for (int in = 0; in < 8; in++)
            #pragma unroll
            for (int q = 0; q < 4; q++) acc[im][in][q] = 0.f;

    load_stage(0, dynb);
    cp_commit();
    load_stage(1, dynb + B2_STAGE);
    cp_commit();
    cp_wait<1>();
    __syncthreads();

    #pragma unroll 1
    for (int chk = 0; chk < NCHK; chk++) {
        const unsigned sb = dynb + (chk & 1) * B2_STAGE;

        #pragma unroll
        for (int ks = 0; ks < 2; ks++) {
            unsigned ah[2][4];
            #pragma unroll
            for (int im = 0; im < 2; im++) {
                int row = wm + im * 16 + (lane & 15);
                unsigned cA = (unsigned)(ks * 2 + (lane >> 4));
                unsigned ad = (unsigned)(row * RSTRIDE) + cA * 16u;
                ldsm4(ah[im], sb + B2_T_A + ad);
            }
            #pragma unroll
            for (int g = 0; g < 4; g++) {
                unsigned bh[4], bl[4];
                int row = wn + g * 16 + ((lane >> 4) * 8) + (lane & 7);
                unsigned cB = (unsigned)(ks * 2 + ((lane >> 3) & 1));
                unsigned bd = (unsigned)(row * RSTRIDE) + cB * 16u;
                ldsm4(bh, sb + B2_T_BH + bd);
                ldsm4(bl, sb + B2_T_BL + bd);
                #pragma unroll
                for (int im = 0; im < 2; im++) {
                    mma16816(acc[im][2 * g],     ah[im], &bh[0]);
                    mma16816(acc[im][2 * g],     ah[im], &bl[0]);
                    mma16816(acc[im][2 * g + 1], ah[im], &bh[2]);
                    mma16816(acc[im][2 * g + 1], ah[im], &bl[2]);
                }
            }
        }
        __syncthreads();
        if (chk + 2 < NCHK) {
            load_stage(chk + 2, sb);
            cp_commit();
            cp_wait<1>();
        } else {
            cp_wait<0>();
        }
        __syncthreads();
    }

    // epilogue: z = (yh+yl) + relu(acc + bias) -> g_x fp32
    #pragma unroll
    for (int im = 0; im < 2; im++) {
        int r0 = bm * 128 + wm + im * 16 + (lane >> 2);
        #pragma unroll
        for (int in = 0; in < 8; in++) {
            int col = bn * 128 + wn + in * 8 + (lane & 3) * 2;
            float bv0 = bias[col], bv1 = bias[col + 1];
            #pragma unroll
            for (int half = 0; half < 2; half++) {
                int row = r0 + half * 8;
                float v0 = acc[im][in][2 * half + 0] + bv0;
                float v1 = acc[im][in][2 * half + 1] + bv1;
                size_t gi = (size_t)row * D_MODEL + col;
                unsigned ryh = *(const unsigned*)(g_yh + gi);
                unsigned ryl = *(const unsigned*)(g_yl + gi);
                float2 yh = __half22float2(*(__half2*)&ryh);
                float2 yl = __half22float2(*(__half2*)&ryl);
                float o0 = (yh.x + yl.x) + fmaxf(v0, 0.0f);
                float o1 = (yh.y + yl.y) + fmaxf(v1, 0.0f);
                *(float2*)(g_x + gi) = make_float2(o0, o1);
            }
        }
    }
}

// ---------------- driver ---------------------------------------------------------
extern "C" void kernel_launch(void* const* d_in, const int* in_sizes, int n_in,
                              void* d_out, int out_size)
{
    const float* x    = (const float*)d_in[0];
    const float* Wv   = (const float*)d_in[1];
    const float* bv   = (const float*)d_in[2];
    const float* cw   = (const float*)d_in[3];
    const float* cb   = (const float*)d_in[4];
    const float* Wo   = (const float*)d_in[5];
    const float* bo   = (const float*)d_in[6];
    const float* a1   = (const float*)d_in[7];
    const float* b1   = (const float*)d_in[8];
    const float* a2   = (const float*)d_in[9];
    const float* b2   = (const float*)d_in[10];
    float* out = (float*)d_out;

    cudaFuncSetAttribute(gemm_a3_kernel, cudaFuncAttributeMaxDynamicSharedMemorySize, A3_DYN);
    cudaFuncSetAttribute(gemm_b2_kernel, cudaFuncAttributeMaxDynamicSharedMemorySize, B2_DYN);

    // one-shot Wv split (deterministic; re-run every call)
    convert_w_kernel<<<(N_LAYERS * D_MODEL * D_MODEL) / 256, 256>>>(Wv);
    // y = norm1(x) for layer 0
    norm_first_kernel<<<ROWS / 8, 256>>>(x, a1, b1);

    for (int L = 0; L < N_LAYERS; L++) {
        // ksum / scores / fused weights
        colsum_kernel<<<BS * 2 * SCHUNKS, 256>>>();
        ksum_reduce_kernel<<<32, 256>>>();
        scores_kernel<<<BS * HEADS, 64>>>(cw + L * DK, cb + L * DK);
        make_wt_kernel<<<BS * HEADS, 256>>>(Wo + (size_t)L * D_MODEL * D_MODEL);
        // v = y @ Wv^T + bv     (3-term: y exact)
        gemm_a3_kernel<<<dim3(4, 512), 256, A3_DYN>>>(L, bv + L * D_MODEL);
        // z = y + relu(v @ W~^T + bo)   (2-term; outmm fused into W~)
        gemm_b2_kernel<<<dim3(4, 512), 256, B2_DYN>>>(bo + L * D_MODEL);
        // norms
        if (L < N_LAYERS - 1) {
            norm_fused_kernel<<<ROWS / 8, 256>>>(a2 + L * D_MODEL, b2 + L * D_MODEL,
                                                 a1 + (L + 1) * D_MODEL,
                                                 b1 + (L + 1) * D_MODEL);
        } else {
            norm_last_kernel<<<ROWS / 8, 256>>>(a2 + L * D_MODEL, b2 + L * D_MODEL, out);
        }
    }
}